// round 6
// baseline (speedup 1.0000x reference)
#include <cuda_runtime.h>
#include <cuda_bf16.h>
#include <math.h>

// Problem constants
#define B_    256
#define N_    512
#define HID_  512
#define IN_   57
#define OUT_  57

// Launch geometry: 16 clusters x 8 CTAs = 128 CTAs (one per SM, co-resident).
#define CPC         8                         // CTAs per cluster
#define CLUSTERS    16
#define GRID_       (CLUSTERS * CPC)
#define THREADS_    256
#define BPC         (B_ / CLUSTERS)           // 16 batches per cluster
#define COLS        (HID_ / CPC)              // 64 output cols per CTA
#define KSPLIT      4
#define KCH         (HID_ / KSPLIT)           // 128 k per thread
#define NPAIRCOL    (COLS / 2)                // 32 column-pairs per CTA

// Hidden-state history: H[b][n][k], n in [0, N]; row N is the zero sentinel
// (never written; __device__ globals are zero-initialized). ~269 MB.
__device__ float g_H[(size_t)B_ * (N_ + 1) * HID_];

// Dynamic SMEM layout (bytes)
#define SM_WHS   0                              // Wh slice [512][64] f32 = 131072
#define SM_ST    131072                         // s^T      [512][16] f32 = 32768
#define SM_RED   (131072 + 32768)               // partials [4][16][32] u64 = 16384
#define SM_BIH   (SM_RED + 16384)               // b_ih slice [64] f32 = 256
#define SM_TOTAL (SM_BIH + 256)                 // 180480 bytes

// ---- packed f32x2 helpers (FFMA2 path: only reachable via PTX) ----
__device__ __forceinline__ unsigned long long pack2(float x, float y) {
    unsigned long long r;
    asm("mov.b64 %0, {%1, %2};" : "=l"(r) : "f"(x), "f"(y));
    return r;
}
__device__ __forceinline__ float2 unpack2(unsigned long long v) {
    float2 f;
    asm("mov.b64 {%0, %1}, %2;" : "=f"(f.x), "=f"(f.y) : "l"(v));
    return f;
}
__device__ __forceinline__ void fma2(unsigned long long& d,
                                     unsigned long long a,
                                     unsigned long long b) {
    asm("fma.rn.f32x2 %0, %1, %2, %0;" : "+l"(d) : "l"(a), "l"(b));
}

// ============================================================================
// Main persistent kernel: 512 steps, cluster-synchronized.
//   cluster cl  -> batches [cl*16, cl*16+16)
//   CTA rank r  -> output columns [r*64, r*64+64), Wh slice resident in SMEM
// Per step:
//   1) gather s[b] = H[b][li] + H[b][ri] into sT[k][b] (transposed, SMEM)
//   2) GEMM (16 x 64 x 512) via fma.rn.f32x2, K split 4-way across threads
//   3) K-reduce in SMEM, add Wx[value] + b_ih, tanh, store h to g_H
//   4) threadfence + barrier.cluster
// ============================================================================
extern "C" __global__ void __launch_bounds__(THREADS_, 1) __cluster_dims__(CPC, 1, 1)
rnn_main(const int* __restrict__ left_idx,
         const int* __restrict__ right_idx,
         const int* __restrict__ values,
         const float* __restrict__ W_ih,
         const float* __restrict__ b_ih)
{
    extern __shared__ char smem[];
    float*              Whs = (float*)(smem + SM_WHS);               // [512][64]
    float*              sT  = (float*)(smem + SM_ST);                // [512][16]
    unsigned long long* red = (unsigned long long*)(smem + SM_RED);  // [4][16][32]
    float*              bih = (float*)(smem + SM_BIH);               // [64]

    const int tid   = threadIdx.x;
    const int rank  = blockIdx.x & (CPC - 1);
    const int cl    = blockIdx.x >> 3;
    const int bbase = cl * BPC;
    const int cbase = rank * COLS;

    // ---- Load resident Wh slice (rows 0..511, cols cbase..cbase+63) ----
    {
        const float* Wh = W_ih + IN_ * HID_;
        const int lane16 = tid & 15;   // 16 threads cover one 64-col row (4x f4)
        const int krow0  = tid >> 4;   // 16 rows per pass
        for (int k = krow0; k < HID_; k += 16) {
            float4 v = *(const float4*)(Wh + (size_t)k * HID_ + cbase + lane16 * 4);
            *(float4*)(Whs + k * COLS + lane16 * 4) = v;
        }
        if (tid < COLS) bih[tid] = b_ih[cbase + tid];
    }

    // ---- Per-thread GEMM tile mapping: 2 batches x 8 cols, K split 4-way ----
    const int ks = tid >> 6;          // 0..3   (K slice)
    const int r6 = tid & 63;
    const int bp = r6 >> 3;           // 0..7   (batch pair: local batches 2bp, 2bp+1)
    const int cp = r6 & 7;            // 0..7   (8-col group: cols 8cp..8cp+7)
    const int k0 = ks * KCH;

    // ---- Gather mapping: 16 batches x 16 k-chunks (32 k each) ----
    const int glb = tid & 15;                 // local batch
    const int gkc = tid >> 4;                 // k-chunk
    const int gb  = bbase + glb;              // global batch
    const float* Hbase = g_H + (size_t)gb * (N_ + 1) * HID_;

    __syncthreads();

    for (int i = 0; i < N_; ++i) {
        // ---- Phase 1: gather s = h[left] + h[right], store transposed ----
        {
            int l = __ldg(left_idx  + gb * N_ + i); if (l < 0) l = N_;
            int r = __ldg(right_idx + gb * N_ + i); if (r < 0) r = N_;
            const float4* hl = (const float4*)(Hbase + (size_t)l * HID_) + gkc * 8;
            const float4* hr = (const float4*)(Hbase + (size_t)r * HID_) + gkc * 8;
            #pragma unroll
            for (int j = 0; j < 8; ++j) {
                float4 a = __ldcg(hl + j);   // L1-bypass: L2 is the coherence point
                float4 b = __ldcg(hr + j);
                float* d = sT + (gkc * 32 + j * 4) * 16 + glb;
                d[0]  = a.x + b.x;
                d[16] = a.y + b.y;
                d[32] = a.z + b.z;
                d[48] = a.w + b.w;
            }
        }
        __syncthreads();

        // ---- Phase 2: GEMM mainloop (fma.rn.f32x2, col-paired accumulators) ----
        unsigned long long acc[8];
        #pragma unroll
        for (int j = 0; j < 8; ++j) acc[j] = 0ULL;
        {
            const float* sp = sT + 2 * bp;
            const float* wp = Whs + cp * 8;
            #pragma unroll 4
            for (int k = k0; k < k0 + KCH; ++k) {
                float2 sv = *(const float2*)(sp + k * 16);
                unsigned long long ps0 = pack2(sv.x, sv.x);
                unsigned long long ps1 = pack2(sv.y, sv.y);
                ulonglong2 wa = *(const ulonglong2*)(wp + k * COLS);
                ulonglong2 wb = *(const ulonglong2*)(wp + k * COLS + 4);
                fma2(acc[0], ps0, wa.x); fma2(acc[1], ps0, wa.y);
                fma2(acc[2], ps0, wb.x); fma2(acc[3], ps0, wb.y);
                fma2(acc[4], ps1, wa.x); fma2(acc[5], ps1, wa.y);
                fma2(acc[6], ps1, wb.x); fma2(acc[7], ps1, wb.y);
            }
        }
        // write partials: red[ks][localb][colpair]
        {
            unsigned long long* rp = red + (size_t)ks * (16 * NPAIRCOL);
            #pragma unroll
            for (int j = 0; j < 4; ++j) {
                rp[(2 * bp)     * NPAIRCOL + cp * 4 + j] = acc[j];
                rp[(2 * bp + 1) * NPAIRCOL + cp * 4 + j] = acc[4 + j];
            }
        }
        __syncthreads();

        // ---- Phase 3: K-reduce + epilogue (Wx row + b_ih, tanh, store h) ----
        {
            const int o   = tid * 2;          // first of two col-pair outputs
            const int lb  = o >> 5;           // local batch 0..15
            const int cpi = o & 31;           // col-pair index (even)
            float4 s = make_float4(0.f, 0.f, 0.f, 0.f);
            #pragma unroll
            for (int q = 0; q < KSPLIT; ++q) {
                const unsigned long long* rp =
                    red + (size_t)q * (16 * NPAIRCOL) + lb * NPAIRCOL + cpi;
                float2 a = unpack2(rp[0]);
                float2 b = unpack2(rp[1]);
                s.x += a.x; s.y += a.y; s.z += b.x; s.w += b.y;
            }
            const int b   = bbase + lb;
            const int cgl = cbase + cpi * 2;          // 4 consecutive global cols
            const int v   = __ldg(values + b * N_ + i);
            float4 x  = *(const float4*)(W_ih + (size_t)v * HID_ + cgl);
            float4 bi = *(const float4*)(bih + cpi * 2);
            float4 h;
            h.x = tanhf(s.x + x.x + bi.x);
            h.y = tanhf(s.y + x.y + bi.y);
            h.z = tanhf(s.z + x.z + bi.z);
            h.w = tanhf(s.w + x.w + bi.w);
            *(float4*)(g_H + ((size_t)b * (N_ + 1) + i) * HID_ + cgl) = h;
        }

        // ---- Phase 4: make h visible, sync the cluster ----
        __threadfence();
        asm volatile("barrier.cluster.arrive.aligned;" ::: "memory");
        asm volatile("barrier.cluster.wait.aligned;"   ::: "memory");
    }
}

// ============================================================================
// Output kernel: logits = h_root @ W_o + b_o, then log_softmax. One block/batch.
// ============================================================================
extern "C" __global__ void __launch_bounds__(64)
rnn_out(const float* __restrict__ W_o,
        const float* __restrict__ b_o,
        float* __restrict__ out)
{
    __shared__ float hs[HID_];
    __shared__ float lg[OUT_];
    __shared__ float lse;
    const int b   = blockIdx.x;
    const int tid = threadIdx.x;

    const float* hrow = g_H + ((size_t)b * (N_ + 1) + (N_ - 1)) * HID_;
    #pragma unroll
    for (int j = 0; j < 2; ++j) {
        float4 v = *(const float4*)(hrow + tid * 8 + j * 4);
        *(float4*)(hs + tid * 8 + j * 4) = v;
    }
    __syncthreads();

    if (tid < OUT_) {
        float acc = b_o[tid];
        #pragma unroll 8
        for (int k = 0; k < HID_; ++k)
            acc = fmaf(hs[k], __ldg(W_o + (size_t)k * OUT_ + tid), acc);
        lg[tid] = acc;
    }
    __syncthreads();

    if (tid == 0) {
        float m = -1e30f;
        for (int j = 0; j < OUT_; ++j) m = fmaxf(m, lg[j]);
        float ssum = 0.f;
        for (int j = 0; j < OUT_; ++j) ssum += expf(lg[j] - m);
        lse = m + logf(ssum);
    }
    __syncthreads();

    if (tid < OUT_) out[(size_t)b * OUT_ + tid] = lg[tid] - lse;
}

// ============================================================================
// Launcher: two kernel nodes, graph-capturable, no allocations.
// ============================================================================
extern "C" void kernel_launch(void* const* d_in, const int* in_sizes, int n_in,
                              void* d_out, int out_size)
{
    (void)in_sizes; (void)n_in; (void)out_size;
    const int*   left  = (const int*)d_in[0];
    const int*   right = (const int*)d_in[1];
    const int*   vals  = (const int*)d_in[2];
    const float* W_ih  = (const float*)d_in[3];
    const float* b_ih  = (const float*)d_in[4];
    const float* W_o   = (const float*)d_in[5];
    const float* b_o   = (const float*)d_in[6];
    float*       out   = (float*)d_out;

    cudaFuncSetAttribute(rnn_main,
                         cudaFuncAttributeMaxDynamicSharedMemorySize, SM_TOTAL);

    rnn_main<<<GRID_, THREADS_, SM_TOTAL>>>(left, right, vals, W_ih, b_ih);
    rnn_out<<<B_, 64>>>(W_o, b_o, out);
}

// round 7
// speedup vs baseline: 3.1808x; 3.1808x over previous
#include <cuda_runtime.h>
#include <math.h>

// Problem constants
#define B_    256
#define N_    512
#define HID_  512
#define IN_   57
#define OUT_  57

#define MAXL      513            // levels 0..512
#define GRID_MAIN 148            // 1 CTA/SM, all co-resident (SMEM-limited)
#define THR_MAIN  256
#define MT        64             // nodes (rows) per GEMM tile

// ---------------- device globals (static, allocation-free) ----------------
__device__ float          g_H[(size_t)B_ * (N_ + 1) * HID_];   // row N = zero sentinel
__device__ unsigned short g_lvl[B_ * N_];
__device__ int            g_cntb[MAXL * B_];    // [lvl][b]
__device__ int            g_base[MAXL * B_];    // [lvl][b] absolute start
__device__ int            g_off[MAXL + 1];
__device__ int            g_nodes[B_ * N_];     // (b<<9)|i, sorted by level
__device__ int            g_nlv;
__device__ unsigned       g_barcnt;
__device__ unsigned       g_epoch;

// ---------------- packed f32x2 helpers (FFMA2 via PTX) ----------------
__device__ __forceinline__ unsigned long long pack2(float x, float y) {
    unsigned long long r;
    asm("mov.b64 %0, {%1, %2};" : "=l"(r) : "f"(x), "f"(y));
    return r;
}
__device__ __forceinline__ float2 unpack2(unsigned long long v) {
    float2 f;
    asm("mov.b64 {%0, %1}, %2;" : "=f"(f.x), "=f"(f.y) : "l"(v));
    return f;
}
__device__ __forceinline__ void fma2(unsigned long long& d,
                                     unsigned long long a,
                                     unsigned long long b) {
    asm("fma.rn.f32x2 %0, %1, %2, %0;" : "+l"(d) : "l"(a), "l"(b));
}

// ============================================================================
// P1: per-batch level computation + per-(level,batch) histogram
// ============================================================================
extern "C" __global__ void __launch_bounds__(128)
k_levels(const int* __restrict__ L, const int* __restrict__ R)
{
    __shared__ int sli[N_], sri[N_], shist[MAXL];
    __shared__ unsigned short slv[N_];
    const int b = blockIdx.x, tid = threadIdx.x;
    for (int i = tid; i < N_; i += 128) { sli[i] = L[b * N_ + i]; sri[i] = R[b * N_ + i]; }
    for (int i = tid; i < MAXL; i += 128) shist[i] = 0;
    __syncthreads();
    if (tid == 0) {
        for (int i = 0; i < N_; ++i) {
            const int l = sli[i], r = sri[i];
            const int a = (l < 0) ? 0 : (int)slv[l];
            const int c = (r < 0) ? 0 : (int)slv[r];
            const int lv = 1 + (a > c ? a : c);
            slv[i] = (unsigned short)lv;
            shist[lv]++;
        }
    }
    __syncthreads();
    for (int i = tid; i < N_; i += 128) g_lvl[b * N_ + i] = slv[i];
    for (int l = tid; l < MAXL; l += 128) g_cntb[l * B_ + b] = shist[l];
}

// ============================================================================
// P2: level totals, offsets, per-(level,batch) bases
// ============================================================================
extern "C" __global__ void __launch_bounds__(256)
k_prefix()
{
    __shared__ int tot[MAXL];
    __shared__ int offs[MAXL + 1];
    const int tid = threadIdx.x;
    for (int l = tid; l < MAXL; l += 256) {
        int run = 0; const int base = l * B_;
        #pragma unroll 4
        for (int b = 0; b < B_; ++b) { const int c = g_cntb[base + b]; g_base[base + b] = run; run += c; }
        tot[l] = run;
    }
    __syncthreads();
    if (tid == 0) {
        int run = 0, mx = 1;
        for (int l = 0; l < MAXL; ++l) { offs[l] = run; run += tot[l]; if (tot[l] > 0) mx = l; }
        offs[MAXL] = run;
        g_nlv = mx;
    }
    __syncthreads();
    for (int idx = tid; idx < MAXL * B_; idx += 256) g_base[idx] += offs[idx >> 8];  // B_=256
    for (int l = tid; l <= MAXL; l += 256) g_off[l] = offs[l];
}

// ============================================================================
// P3: counting-sort scatter of (b,i) node ids into level order
// ============================================================================
extern "C" __global__ void __launch_bounds__(128)
k_scatter()
{
    __shared__ unsigned short slv[N_];
    __shared__ int cur[MAXL];
    __shared__ int pos[N_];
    const int b = blockIdx.x, tid = threadIdx.x;
    for (int i = tid; i < N_; i += 128) slv[i] = g_lvl[b * N_ + i];
    for (int l = tid; l < MAXL; l += 128) cur[l] = g_base[l * B_ + b];
    __syncthreads();
    if (tid == 0)
        for (int i = 0; i < N_; ++i) { const int l = slv[i]; pos[i] = cur[l]++; }
    __syncthreads();
    for (int i = tid; i < N_; i += 128) g_nodes[pos[i]] = (b << 9) | i;
}

// ============================================================================
// Grid-wide software barrier (all GRID_MAIN CTAs co-resident by construction)
// ============================================================================
__device__ __forceinline__ void grid_barrier(unsigned tgt, unsigned nct)
{
    __syncthreads();
    if (threadIdx.x == 0) {
        __threadfence();                              // release h writes
        const unsigned a = atomicAdd(&g_barcnt, 1u);
        if (a == nct - 1u) {
            g_barcnt = 0u;
            __threadfence();
            atomicExch(&g_epoch, tgt);
        } else {
            unsigned e;
            do {
                asm volatile("ld.acquire.gpu.u32 %0, [%1];"
                             : "=r"(e) : "l"((unsigned*)&g_epoch) : "memory");
                if (e >= tgt) break;
                __nanosleep(128u);
            } while (true);
        }
    }
    __syncthreads();
}

// ============================================================================
// Main persistent kernel: level-parallel batched GEMM + tanh.
// CTA tile: 64 nodes x 512 cols, K=512. A (gathered h_l+h_r) transposed in
// SMEM; Wh streamed from L2; fp32x2 packed FMA mainloop.
// Thread tile: 8 rows x 16 cols (rg = tid&7 -> rows, cg = tid>>3 -> cols).
// ============================================================================
#define SMEM_MAIN (MT * HID_ * 4 + 4 * MT * 4 + HID_ * 4)   // 134144 B

__device__ __forceinline__ void fma_block(unsigned long long* acc,
                                          const float4& a0, const float4& a1,
                                          const ulonglong2& w0, const ulonglong2& w1,
                                          const ulonglong2& w2, const ulonglong2& w3)
{
    unsigned long long p[8];
    p[0] = pack2(a0.x, a0.x); p[1] = pack2(a0.y, a0.y);
    p[2] = pack2(a0.z, a0.z); p[3] = pack2(a0.w, a0.w);
    p[4] = pack2(a1.x, a1.x); p[5] = pack2(a1.y, a1.y);
    p[6] = pack2(a1.z, a1.z); p[7] = pack2(a1.w, a1.w);
    #pragma unroll
    for (int rj = 0; rj < 8; ++rj) {
        const unsigned long long pr = p[rj];
        fma2(acc[rj * 8 + 0], pr, w0.x);
        fma2(acc[rj * 8 + 1], pr, w0.y);
        fma2(acc[rj * 8 + 2], pr, w1.x);
        fma2(acc[rj * 8 + 3], pr, w1.y);
        fma2(acc[rj * 8 + 4], pr, w2.x);
        fma2(acc[rj * 8 + 5], pr, w2.y);
        fma2(acc[rj * 8 + 6], pr, w3.x);
        fma2(acc[rj * 8 + 7], pr, w3.y);
    }
}

extern "C" __global__ void __launch_bounds__(THR_MAIN, 1)
rnn_main(const int* __restrict__ L, const int* __restrict__ R,
         const int* __restrict__ V, const float* __restrict__ W_ih,
         const float* __restrict__ b_ih)
{
    extern __shared__ float sm[];
    float* AsT = sm;                            // [512][64]  (k-major, node minor)
    int*   il  = (int*)(sm + MT * HID_);        // [64] gather row (left)  or -1
    int*   ir  = il + MT;                       // [64] gather row (right)
    int*   iv  = ir + MT;                       // [64] value (one-hot row)
    int*   io  = iv + MT;                       // [64] output row b*(N+1)+i
    float* bih = (float*)(io + MT);             // [512]

    const int tid = threadIdx.x;
    for (int i = tid; i < HID_; i += THR_MAIN) bih[i] = b_ih[i];

    const int rg = tid & 7, cg = tid >> 3;
    const int r0 = rg * 8;
    const int c0 = cg * 16;
    const float* Wh = W_ih + IN_ * HID_;
    const int nlv = g_nlv;
    const unsigned nct = gridDim.x;

    for (int lvl = 1; lvl <= nlv; ++lvl) {
        const int s = g_off[lvl], e = g_off[lvl + 1];
        for (int t0 = s + blockIdx.x * MT; t0 < e; t0 += (int)nct * MT) {
            // ---- node metadata ----
            if (tid < MT) {
                const int gi = t0 + tid;
                if (gi < e) {
                    const int nd = g_nodes[gi];
                    const int b = nd >> 9, i = nd & (N_ - 1);
                    int l = L[b * N_ + i]; if (l < 0) l = N_;
                    int r = R[b * N_ + i]; if (r < 0) r = N_;
                    il[tid] = b * (N_ + 1) + l;
                    ir[tid] = b * (N_ + 1) + r;
                    iv[tid] = V[b * N_ + i];
                    io[tid] = b * (N_ + 1) + i;
                } else {
                    il[tid] = -1;
                }
            }
            __syncthreads();

            // ---- gather s = h[l] + h[r], transposed into SMEM ----
            {
                const int nd = tid & 63, kc = tid >> 6;   // 4 k-chunks of 128
                const int lr = il[nd];
                if (lr >= 0) {
                    const float4* hl = (const float4*)(g_H + (size_t)lr * HID_) + kc * 32;
                    const float4* hr = (const float4*)(g_H + (size_t)ir[nd] * HID_) + kc * 32;
                    float* d0 = AsT + (kc * 128) * MT + nd;
                    #pragma unroll 4
                    for (int j = 0; j < 32; ++j) {
                        const float4 a  = __ldcg(hl + j);   // L2 is coherence point
                        const float4 b4 = __ldcg(hr + j);
                        float* d = d0 + j * (4 * MT);
                        d[0 * MT] = a.x + b4.x;
                        d[1 * MT] = a.y + b4.y;
                        d[2 * MT] = a.z + b4.z;
                        d[3 * MT] = a.w + b4.w;
                    }
                }
            }
            __syncthreads();

            // ---- GEMM 64 x 512 x 512 (fp32x2), Wh streamed, A in SMEM ----
            unsigned long long acc[64];
            #pragma unroll
            for (int j = 0; j < 64; ++j) acc[j] = 0ULL;
            {
                const float* ap = AsT + r0;
                const float* wp = Wh + c0;
                float4 a0 = *(const float4*)(ap);
                float4 a1 = *(const float4*)(ap + 4);
                ulonglong2 w0 = *(const ulonglong2*)(wp);
                ulonglong2 w1 = *(const ulonglong2*)(wp + 4);
                ulonglong2 w2 = *(const ulonglong2*)(wp + 8);
                ulonglong2 w3 = *(const ulonglong2*)(wp + 12);
                #pragma unroll 2
                for (int k = 0; k < HID_ - 1; ++k) {
                    const float4 na0 = *(const float4*)(ap + MT);
                    const float4 na1 = *(const float4*)(ap + MT + 4);
                    const ulonglong2 nw0 = *(const ulonglong2*)(wp + HID_);
                    const ulonglong2 nw1 = *(const ulonglong2*)(wp + HID_ + 4);
                    const ulonglong2 nw2 = *(const ulonglong2*)(wp + HID_ + 8);
                    const ulonglong2 nw3 = *(const ulonglong2*)(wp + HID_ + 12);
                    fma_block(acc, a0, a1, w0, w1, w2, w3);
                    a0 = na0; a1 = na1; w0 = nw0; w1 = nw1; w2 = nw2; w3 = nw3;
                    ap += MT; wp += HID_;
                }
                fma_block(acc, a0, a1, w0, w1, w2, w3);   // k = 511
            }

            // ---- epilogue: + Wx[value] + b_ih, tanh, store h ----
            #pragma unroll
            for (int rj = 0; rj < 8; ++rj) {
                const int nd = r0 + rj;
                if (il[nd] < 0) continue;
                const float* wx = W_ih + (size_t)iv[nd] * HID_ + c0;
                float* hp = g_H + (size_t)io[nd] * HID_ + c0;
                #pragma unroll
                for (int q = 0; q < 4; ++q) {
                    const float2 v0 = unpack2(acc[rj * 8 + q * 2]);
                    const float2 v1 = unpack2(acc[rj * 8 + q * 2 + 1]);
                    const float4 x  = *(const float4*)(wx + q * 4);
                    const float4 bb = *(const float4*)(bih + c0 + q * 4);
                    float4 o;
                    o.x = tanhf(v0.x + x.x + bb.x);
                    o.y = tanhf(v0.y + x.y + bb.y);
                    o.z = tanhf(v1.x + x.z + bb.z);
                    o.w = tanhf(v1.y + x.w + bb.w);
                    *(float4*)(hp + q * 4) = o;
                }
            }
            __syncthreads();   // protect AsT/meta before next tile
        }
        grid_barrier((unsigned)lvl, nct);
    }
}

// ============================================================================
// Barrier state reset (runs after rnn_main; keeps graph replays deterministic)
// ============================================================================
extern "C" __global__ void k_reset()
{
    if (threadIdx.x == 0) { g_epoch = 0u; g_barcnt = 0u; }
}

// ============================================================================
// Output kernel: logits = h_root @ W_o + b_o, then log_softmax
// ============================================================================
extern "C" __global__ void __launch_bounds__(64)
rnn_out(const float* __restrict__ W_o,
        const float* __restrict__ b_o,
        float* __restrict__ out)
{
    __shared__ float hs[HID_];
    __shared__ float lg[OUT_];
    __shared__ float lse;
    const int b   = blockIdx.x;
    const int tid = threadIdx.x;

    const float* hrow = g_H + ((size_t)b * (N_ + 1) + (N_ - 1)) * HID_;
    #pragma unroll
    for (int j = 0; j < 2; ++j) {
        const float4 v = *(const float4*)(hrow + tid * 8 + j * 4);
        *(float4*)(hs + tid * 8 + j * 4) = v;
    }
    __syncthreads();

    if (tid < OUT_) {
        float acc = b_o[tid];
        #pragma unroll 8
        for (int k = 0; k < HID_; ++k)
            acc = fmaf(hs[k], __ldg(W_o + (size_t)k * OUT_ + tid), acc);
        lg[tid] = acc;
    }
    __syncthreads();

    if (tid == 0) {
        float m = -1e30f;
        for (int j = 0; j < OUT_; ++j) m = fmaxf(m, lg[j]);
        float ssum = 0.f;
        for (int j = 0; j < OUT_; ++j) ssum += expf(lg[j] - m);
        lse = m + logf(ssum);
    }
    __syncthreads();

    if (tid < OUT_) out[(size_t)b * OUT_ + tid] = lg[tid] - lse;
}

// ============================================================================
// Launcher: 6 graph nodes, capturable, allocation-free.
// ============================================================================
extern "C" void kernel_launch(void* const* d_in, const int* in_sizes, int n_in,
                              void* d_out, int out_size)
{
    (void)in_sizes; (void)n_in; (void)out_size;
    const int*   left  = (const int*)d_in[0];
    const int*   right = (const int*)d_in[1];
    const int*   vals  = (const int*)d_in[2];
    const float* W_ih  = (const float*)d_in[3];
    const float* b_ih  = (const float*)d_in[4];
    const float* W_o   = (const float*)d_in[5];
    const float* b_o   = (const float*)d_in[6];
    float*       out   = (float*)d_out;

    cudaFuncSetAttribute(rnn_main,
                         cudaFuncAttributeMaxDynamicSharedMemorySize, SMEM_MAIN);

    k_levels<<<B_, 128>>>(left, right);
    k_prefix<<<1, 256>>>();
    k_scatter<<<B_, 128>>>();
    rnn_main<<<GRID_MAIN, THR_MAIN, SMEM_MAIN>>>(left, right, vals, W_ih, b_ih);
    k_reset<<<1, 1>>>();
    rnn_out<<<B_, 64>>>(W_o, b_o, out);
}

// round 8
// speedup vs baseline: 3.8601x; 1.2136x over previous
#include <cuda_runtime.h>
#include <math.h>

// Problem constants
#define B_    256
#define N_    512
#define HID_  512
#define IN_   57
#define OUT_  57

#define MAXL      513            // levels 0..512
#define GRID_MAIN 296            // 2 CTAs/SM x 148 SMs, all co-resident (SMEM-limited)
#define THR_MAIN  256
#define MT        32             // nodes (rows) per GEMM tile
#define NCH       64             // K chunks of 8 rows

// ---------------- device globals (static, allocation-free) ----------------
__device__ float          g_H[(size_t)B_ * (N_ + 1) * HID_];   // row N = zero sentinel
__device__ unsigned short g_lvl[B_ * N_];
__device__ int            g_cntb[MAXL * B_];    // [lvl][b]
__device__ int            g_base[MAXL * B_];    // [lvl][b] absolute start
__device__ int            g_off[MAXL + 1];
__device__ int            g_nodes[B_ * N_];     // (b<<9)|i, sorted by level
__device__ int            g_nlv;
__device__ unsigned       g_barcnt;
__device__ unsigned       g_epoch;

// ---------------- packed f32x2 helpers (FFMA2 via PTX) ----------------
__device__ __forceinline__ unsigned long long pack2(float x, float y) {
    unsigned long long r;
    asm("mov.b64 %0, {%1, %2};" : "=l"(r) : "f"(x), "f"(y));
    return r;
}
__device__ __forceinline__ float2 unpack2(unsigned long long v) {
    float2 f;
    asm("mov.b64 {%0, %1}, %2;" : "=f"(f.x), "=f"(f.y) : "l"(v));
    return f;
}
__device__ __forceinline__ void fma2(unsigned long long& d,
                                     unsigned long long a,
                                     unsigned long long b) {
    asm("fma.rn.f32x2 %0, %1, %2, %0;" : "+l"(d) : "l"(a), "l"(b));
}

// ---------------- cp.async helpers ----------------
__device__ __forceinline__ void cp16(unsigned int dst, const void* src) {
    asm volatile("cp.async.cg.shared.global [%0], [%1], 16;" :: "r"(dst), "l"(src));
}
__device__ __forceinline__ void cp_commit() { asm volatile("cp.async.commit_group;" ::: "memory"); }
__device__ __forceinline__ void cp_wait1()  { asm volatile("cp.async.wait_group 1;" ::: "memory"); }
__device__ __forceinline__ void cp_wait0()  { asm volatile("cp.async.wait_group 0;" ::: "memory"); }

// ============================================================================
// P1: per-batch level computation + per-(level,batch) histogram
// ============================================================================
extern "C" __global__ void __launch_bounds__(128)
k_levels(const int* __restrict__ L, const int* __restrict__ R)
{
    __shared__ int sli[N_], sri[N_], shist[MAXL];
    __shared__ unsigned short slv[N_];
    const int b = blockIdx.x, tid = threadIdx.x;
    for (int i = tid; i < N_; i += 128) { sli[i] = L[b * N_ + i]; sri[i] = R[b * N_ + i]; }
    for (int i = tid; i < MAXL; i += 128) shist[i] = 0;
    __syncthreads();
    if (tid == 0) {
        for (int i = 0; i < N_; ++i) {
            const int l = sli[i], r = sri[i];
            const int a = (l < 0) ? 0 : (int)slv[l];
            const int c = (r < 0) ? 0 : (int)slv[r];
            const int lv = 1 + (a > c ? a : c);
            slv[i] = (unsigned short)lv;
            shist[lv]++;
        }
    }
    __syncthreads();
    for (int i = tid; i < N_; i += 128) g_lvl[b * N_ + i] = slv[i];
    for (int l = tid; l < MAXL; l += 128) g_cntb[l * B_ + b] = shist[l];
}

// ============================================================================
// P2: level totals, offsets, per-(level,batch) bases
// ============================================================================
extern "C" __global__ void __launch_bounds__(256)
k_prefix()
{
    __shared__ int tot[MAXL];
    __shared__ int offs[MAXL + 1];
    const int tid = threadIdx.x;
    for (int l = tid; l < MAXL; l += 256) {
        int run = 0; const int base = l * B_;
        #pragma unroll 4
        for (int b = 0; b < B_; ++b) { const int c = g_cntb[base + b]; g_base[base + b] = run; run += c; }
        tot[l] = run;
    }
    __syncthreads();
    if (tid == 0) {
        int run = 0, mx = 1;
        for (int l = 0; l < MAXL; ++l) { offs[l] = run; run += tot[l]; if (tot[l] > 0) mx = l; }
        offs[MAXL] = run;
        g_nlv = mx;
    }
    __syncthreads();
    for (int idx = tid; idx < MAXL * B_; idx += 256) g_base[idx] += offs[idx >> 8];  // B_=256
    for (int l = tid; l <= MAXL; l += 256) g_off[l] = offs[l];
}

// ============================================================================
// P3: counting-sort scatter of (b,i) node ids into level order
// ============================================================================
extern "C" __global__ void __launch_bounds__(128)
k_scatter()
{
    __shared__ unsigned short slv[N_];
    __shared__ int cur[MAXL];
    __shared__ int pos[N_];
    const int b = blockIdx.x, tid = threadIdx.x;
    for (int i = tid; i < N_; i += 128) slv[i] = g_lvl[b * N_ + i];
    for (int l = tid; l < MAXL; l += 128) cur[l] = g_base[l * B_ + b];
    __syncthreads();
    if (tid == 0)
        for (int i = 0; i < N_; ++i) { const int l = slv[i]; pos[i] = cur[l]++; }
    __syncthreads();
    for (int i = tid; i < N_; i += 128) g_nodes[pos[i]] = (b << 9) | i;
}

// ============================================================================
// Grid-wide software barrier (all GRID_MAIN CTAs co-resident by construction)
// ============================================================================
__device__ __forceinline__ void grid_barrier(unsigned tgt, unsigned nct)
{
    __syncthreads();
    if (threadIdx.x == 0) {
        __threadfence();                              // release h writes
        const unsigned a = atomicAdd(&g_barcnt, 1u);
        if (a == nct - 1u) {
            g_barcnt = 0u;
            __threadfence();
            atomicExch(&g_epoch, tgt);
        } else {
            unsigned e;
            do {
                asm volatile("ld.acquire.gpu.u32 %0, [%1];"
                             : "=r"(e) : "l"((unsigned*)&g_epoch) : "memory");
                if (e >= tgt) break;
                __nanosleep(64u);
            } while (true);
        }
    }
    __syncthreads();
}

// ============================================================================
// Main persistent kernel: level-parallel batched GEMM + tanh.
// CTA tile: 32 nodes x 512 cols, K=512. A (gathered h_l+h_r) transposed in
// SMEM; Wh staged through warp-private double-buffered SMEM via cp.async.
// Thread tile: 4 rows x 16 cols. fp32x2 packed FMA mainloop (FFMA2).
// 2 CTAs/SM for latency hiding + phase overlap.
// ============================================================================
// SMEM floats: AsT [512][32]=16384 | wbuf 8 warps x 2 buf x 512 = 8192 |
//              bih 512 | meta 4x32 ints
#define SMEM_MAIN (16384*4 + 8192*4 + 512*4 + 4*MT*4)   // 100864 B

extern "C" __global__ void __launch_bounds__(THR_MAIN, 2)
rnn_main(const int* __restrict__ L, const int* __restrict__ R,
         const int* __restrict__ V, const float* __restrict__ W_ih,
         const float* __restrict__ b_ih)
{
    extern __shared__ float sm[];
    float* AsT  = sm;                       // [512][32] k-major, node minor
    float* wball= sm + 16384;               // [8 warps][2 bufs][8 rows][64 cols]
    float* bih  = sm + 16384 + 8192;        // [512]
    int*   il   = (int*)(sm + 16384 + 8192 + 512);
    int*   ir   = il + MT;
    int*   iv   = ir + MT;
    int*   io   = iv + MT;

    const int tid  = threadIdx.x;
    const int wid  = tid >> 5, lane = tid & 31;
    const int rg   = tid & 7,  cg   = tid >> 3;     // rows group / col group
    const int r0   = rg * 4;                        // 4 rows
    const int c0   = cg * 16;                       // 16 cols
    const int cl   = cg & 3;                        // col-chunk within warp

    for (int i = tid; i < HID_; i += THR_MAIN) bih[i] = b_ih[i];

    const float* Wh = W_ih + IN_ * HID_;
    float* wbuf = wball + wid * 1024;               // 2 bufs x 512 floats
    const unsigned wbufs = (unsigned)__cvta_generic_to_shared(wbuf);
    const int nlv = g_nlv;
    const unsigned nct = gridDim.x;

    for (int lvl = 1; lvl <= nlv; ++lvl) {
        const int s = g_off[lvl], e = g_off[lvl + 1];
        for (int t0 = s + blockIdx.x * MT; t0 < e; t0 += (int)nct * MT) {
            // ---- node metadata ----
            if (tid < MT) {
                const int gi = t0 + tid;
                if (gi < e) {
                    const int nd = g_nodes[gi];
                    const int b = nd >> 9, i = nd & (N_ - 1);
                    int l = L[b * N_ + i]; if (l < 0) l = N_;
                    int r = R[b * N_ + i]; if (r < 0) r = N_;
                    il[tid] = b * (N_ + 1) + l;
                    ir[tid] = b * (N_ + 1) + r;
                    iv[tid] = V[b * N_ + i];
                    io[tid] = b * (N_ + 1) + i;
                } else {
                    il[tid] = -1;
                }
            }
            __syncthreads();

            // ---- gather s = h[l] + h[r], transposed into SMEM ----
            {
                const int nd = tid & 31, kc = tid >> 5;   // 8 k-chunks of 64
                const int lr = il[nd];
                if (lr >= 0) {
                    const float4* hl = (const float4*)(g_H + (size_t)lr * HID_) + kc * 16;
                    const float4* hr = (const float4*)(g_H + (size_t)ir[nd] * HID_) + kc * 16;
                    float* d0 = AsT + (kc * 64) * MT + nd;
                    #pragma unroll 4
                    for (int j = 0; j < 16; ++j) {
                        const float4 a  = __ldcg(hl + j);   // L2 is coherence point
                        const float4 b4 = __ldcg(hr + j);
                        float* d = d0 + j * (4 * MT);
                        d[0 * MT] = a.x + b4.x;
                        d[1 * MT] = a.y + b4.y;
                        d[2 * MT] = a.z + b4.z;
                        d[3 * MT] = a.w + b4.w;
                    }
                }
            }
            __syncthreads();

            // ---- GEMM 32 x 512 x 512: W staged via cp.async (warp-private) ----
            unsigned long long acc[32];
            #pragma unroll
            for (int j = 0; j < 32; ++j) acc[j] = 0ULL;

            // prefetch chunk into buf: 8 rows x 64 cols, 4x4-transposed f4 slots
            #define PREFETCH(c, bf)                                              \
            {                                                                    \
                _Pragma("unroll")                                                \
                for (int t = 0; t < 4; ++t) {                                    \
                    const int ee = lane + 32 * t;                                \
                    const int row = ee >> 4, m = ee & 15;                        \
                    const int slt = ((m & 3) << 2) | (m >> 2);                   \
                    cp16(wbufs + (unsigned)(((bf) * 512 + row * 64 + slt * 4) * 4), \
                         Wh + (size_t)((c) * 8 + row) * HID_ + wid * 64 + m * 4);   \
                }                                                                \
                cp_commit();                                                     \
            }

            PREFETCH(0, 0)
            PREFETCH(1, 1)

            for (int c = 0; c < NCH; ++c) {
                if (c + 1 < NCH) cp_wait1(); else cp_wait0();
                __syncwarp();
                const int bf = c & 1;
                const float* wb = wbuf + bf * 512 + cl * 4;
                const float* ab = AsT + (c * 8) * MT + r0;
                #pragma unroll
                for (int kk = 0; kk < 8; ++kk) {
                    const float4 a = *(const float4*)(ab + kk * MT);
                    const float* wr = wb + kk * 64;
                    const ulonglong2 w0 = *(const ulonglong2*)(wr);
                    const ulonglong2 w1 = *(const ulonglong2*)(wr + 16);
                    const ulonglong2 w2 = *(const ulonglong2*)(wr + 32);
                    const ulonglong2 w3 = *(const ulonglong2*)(wr + 48);
                    unsigned long long p[4];
                    p[0] = pack2(a.x, a.x); p[1] = pack2(a.y, a.y);
                    p[2] = pack2(a.z, a.z); p[3] = pack2(a.w, a.w);
                    #pragma unroll
                    for (int rj = 0; rj < 4; ++rj) {
                        const unsigned long long pr = p[rj];
                        fma2(acc[rj * 8 + 0], pr, w0.x);
                        fma2(acc[rj * 8 + 1], pr, w0.y);
                        fma2(acc[rj * 8 + 2], pr, w1.x);
                        fma2(acc[rj * 8 + 3], pr, w1.y);
                        fma2(acc[rj * 8 + 4], pr, w2.x);
                        fma2(acc[rj * 8 + 5], pr, w2.y);
                        fma2(acc[rj * 8 + 6], pr, w3.x);
                        fma2(acc[rj * 8 + 7], pr, w3.y);
                    }
                }
                if (c + 2 < NCH) PREFETCH(c + 2, bf)
            }
            #undef PREFETCH

            // ---- epilogue: + Wx[value] + b_ih, tanh, store h ----
            #pragma unroll
            for (int rj = 0; rj < 4; ++rj) {
                const int nd = r0 + rj;
                if (il[nd] < 0) continue;
                const float* wx = W_ih + (size_t)iv[nd] * HID_ + c0;
                float* hp = g_H + (size_t)io[nd] * HID_ + c0;
                #pragma unroll
                for (int q = 0; q < 4; ++q) {
                    const float2 v0 = unpack2(acc[rj * 8 + q * 2]);
                    const float2 v1 = unpack2(acc[rj * 8 + q * 2 + 1]);
                    const float4 x  = *(const float4*)(wx + q * 4);
                    const float4 bb = *(const float4*)(bih + c0 + q * 4);
                    float4 o;
                    o.x = tanhf(v0.x + x.x + bb.x);
                    o.y = tanhf(v0.y + x.y + bb.y);
                    o.z = tanhf(v1.x + x.z + bb.z);
                    o.w = tanhf(v1.y + x.w + bb.w);
                    *(float4*)(hp + q * 4) = o;
                }
            }
            __syncthreads();   // protect AsT/meta before next tile
        }
        grid_barrier((unsigned)lvl, nct);
    }
}

// ============================================================================
// Barrier state reset (keeps graph replays deterministic)
// ============================================================================
extern "C" __global__ void k_reset()
{
    if (threadIdx.x == 0) { g_epoch = 0u; g_barcnt = 0u; }
}

// ============================================================================
// Output kernel: logits = h_root @ W_o + b_o, then log_softmax
// ============================================================================
extern "C" __global__ void __launch_bounds__(64)
rnn_out(const float* __restrict__ W_o,
        const float* __restrict__ b_o,
        float* __restrict__ out)
{
    __shared__ float hs[HID_];
    __shared__ float lg[OUT_];
    __shared__ float lse;
    const int b   = blockIdx.x;
    const int tid = threadIdx.x;

    const float* hrow = g_H + ((size_t)b * (N_ + 1) + (N_ - 1)) * HID_;
    #pragma unroll
    for (int j = 0; j < 2; ++j) {
        const float4 v = *(const float4*)(hrow + tid * 8 + j * 4);
        *(float4*)(hs + tid * 8 + j * 4) = v;
    }
    __syncthreads();

    if (tid < OUT_) {
        float acc = b_o[tid];
        #pragma unroll 8
        for (int k = 0; k < HID_; ++k)
            acc = fmaf(hs[k], __ldg(W_o + (size_t)k * OUT_ + tid), acc);
        lg[tid] = acc;
    }
    __syncthreads();

    if (tid == 0) {
        float m = -1e30f;
        for (int j = 0; j < OUT_; ++j) m = fmaxf(m, lg[j]);
        float ssum = 0.f;
        for (int j = 0; j < OUT_; ++j) ssum += expf(lg[j] - m);
        lse = m + logf(ssum);
    }
    __syncthreads();

    if (tid < OUT_) out[(size_t)b * OUT_ + tid] = lg[tid] - lse;
}

// ============================================================================
// Launcher: 6 graph nodes, capturable, allocation-free.
// ============================================================================
extern "C" void kernel_launch(void* const* d_in, const int* in_sizes, int n_in,
                              void* d_out, int out_size)
{
    (void)in_sizes; (void)n_in; (void)out_size;
    const int*   left  = (const int*)d_in[0];
    const int*   right = (const int*)d_in[1];
    const int*   vals  = (const int*)d_in[2];
    const float* W_ih  = (const float*)d_in[3];
    const float* b_ih  = (const float*)d_in[4];
    const float* W_o   = (const float*)d_in[5];
    const float* b_o   = (const float*)d_in[6];
    float*       out   = (float*)d_out;

    cudaFuncSetAttribute(rnn_main,
                         cudaFuncAttributeMaxDynamicSharedMemorySize, SMEM_MAIN);

    k_levels<<<B_, 128>>>(left, right);
    k_prefix<<<1, 256>>>();
    k_scatter<<<B_, 128>>>();
    rnn_main<<<GRID_MAIN, THR_MAIN, SMEM_MAIN>>>(left, right, vals, W_ih, b_ih);
    k_reset<<<1, 1>>>();
    rnn_out<<<B_, 64>>>(W_o, b_o, out);
}

// round 10
// speedup vs baseline: 7.3271x; 1.8982x over previous
#include <cuda_runtime.h>
#include <cuda_bf16.h>
#include <math.h>
#include <stdint.h>

// Problem constants
#define B_    256
#define N_    512
#define HID_  512
#define IN_   57
#define OUT_  57

#define MAXL      513
#define GRID_MAIN 148            // 1 CTA/SM, co-resident
#define THR_MAIN  256
#define MT        64             // nodes (rows) per item
#define NHALF     256            // cols per item

// ---------------- device globals ----------------
__device__ float          g_H[(size_t)B_ * (N_ + 1) * HID_];   // row N_ (b=0) = zero sentinel
__device__ __nv_bfloat16  g_Wb_hi[HID_ * HID_];   // fragment-packed Wh^T hi
__device__ __nv_bfloat16  g_Wb_lo[HID_ * HID_];   // fragment-packed Wh^T lo
__device__ unsigned short g_lvl[B_ * N_];
__device__ int            g_cntb[MAXL * B_];
__device__ int            g_base[MAXL * B_];
__device__ int            g_off[MAXL + 1];
__device__ int            g_nodes[B_ * N_];
__device__ int            g_nlv;
__device__ unsigned       g_barcnt;
__device__ unsigned       g_epoch;

// ---------------- SMEM layout ----------------
// A planes: [term hi/lo][2 buf][64 rows][136 bf16] row stride 272 B
#define A_STRIDE 272
#define A_BUFSZ  (MT * A_STRIDE)         // 17408
#define SM_AHI   0                       // 2 * 17408 = 34816
#define SM_ALO   34816                   // 2 * 17408
#define SM_BIH   69632                   // 512 f32 = 2048
#define SM_META  71680                   // il/ir/iv/io [64] each = 1024
#define SMEM_MAIN 72704

// ---------------- PTX helpers (baseline ISA only) ----------------
__device__ __forceinline__ void mma16816(float* d, const uint32_t* a,
                                         uint32_t b0, uint32_t b1) {
    asm volatile(
        "mma.sync.aligned.m16n8k16.row.col.f32.bf16.bf16.f32 "
        "{%0,%1,%2,%3}, {%4,%5,%6,%7}, {%8,%9}, {%0,%1,%2,%3};\n"
        : "+f"(d[0]), "+f"(d[1]), "+f"(d[2]), "+f"(d[3])
        : "r"(a[0]), "r"(a[1]), "r"(a[2]), "r"(a[3]), "r"(b0), "r"(b1));
}
__device__ __forceinline__ void ldsm4(uint32_t* r, uint32_t a) {
    asm volatile("ldmatrix.sync.aligned.m8n8.x4.shared.b16 {%0,%1,%2,%3}, [%4];\n"
        : "=r"(r[0]), "=r"(r[1]), "=r"(r[2]), "=r"(r[3]) : "r"(a));
}
__device__ __forceinline__ uint32_t smem_u32(const void* p) {
    return (uint32_t)__cvta_generic_to_shared(p);
}

// FFMA-only tanh: tanh(x) = 1 - 2/(e^{2x}+1); exp2 via round-trick + deg-7
// Taylor; reciprocal via bit-trick seed + 3 Newton. No MUFU, no CVT.
__device__ __forceinline__ float ftanh(float x) {
    float t = fminf(fmaxf(x, -15.0f), 15.0f);
    float z = t * 2.8853900817779268f;           // 2*log2(e)*x
    float zk = z + 12582912.0f;                   // round-to-nearest-even
    float k  = zk - 12582912.0f;
    float f  = z - k;                             // f in [-0.5, 0.5]
    float p = 1.5252733814e-5f;
    p = fmaf(p, f, 1.5403530394e-4f);
    p = fmaf(p, f, 1.3333558146e-3f);
    p = fmaf(p, f, 9.6181291076e-3f);
    p = fmaf(p, f, 5.5504108664e-2f);
    p = fmaf(p, f, 2.4022650696e-1f);
    p = fmaf(p, f, 6.9314718056e-1f);
    p = fmaf(p, f, 1.0f);
    const int ib = __float_as_int(zk);            // 0x4B400000 + (int)k
    const float sc = __int_as_float((ib + (127 - 0x4B400000)) << 23);   // 2^k
    const float E = p * sc;                       // e^{2x}
    const float d = E + 1.0f;
    float r = __int_as_float(0x7EF311C3 - __float_as_int(d));
    r = r * fmaf(-d, r, 2.0f);
    r = r * fmaf(-d, r, 2.0f);
    r = r * fmaf(-d, r, 2.0f);
    return fmaf(-2.0f, r, 1.0f);
}

// ============================================================================
// Prep kernels
// ============================================================================
extern "C" __global__ void __launch_bounds__(128)
k_levels(const int* __restrict__ L, const int* __restrict__ R)
{
    __shared__ int sli[N_], sri[N_], shist[MAXL];
    __shared__ unsigned short slv[N_];
    const int b = blockIdx.x, tid = threadIdx.x;
    for (int i = tid; i < N_; i += 128) { sli[i] = L[b * N_ + i]; sri[i] = R[b * N_ + i]; }
    for (int i = tid; i < MAXL; i += 128) shist[i] = 0;
    __syncthreads();
    if (tid == 0) {
        for (int i = 0; i < N_; ++i) {
            const int l = sli[i], r = sri[i];
            const int a = (l < 0) ? 0 : (int)slv[l];
            const int c = (r < 0) ? 0 : (int)slv[r];
            const int lv = 1 + (a > c ? a : c);
            slv[i] = (unsigned short)lv;
            shist[lv]++;
        }
    }
    __syncthreads();
    for (int i = tid; i < N_; i += 128) g_lvl[b * N_ + i] = slv[i];
    for (int l = tid; l < MAXL; l += 128) g_cntb[l * B_ + b] = shist[l];
}

extern "C" __global__ void __launch_bounds__(256)
k_prefix()
{
    __shared__ int tot[MAXL];
    __shared__ int offs[MAXL + 1];
    const int tid = threadIdx.x;
    for (int l = tid; l < MAXL; l += 256) {
        int run = 0; const int base = l * B_;
        #pragma unroll 4
        for (int b = 0; b < B_; ++b) { const int c = g_cntb[base + b]; g_base[base + b] = run; run += c; }
        tot[l] = run;
    }
    __syncthreads();
    if (tid == 0) {
        int run = 0, mx = 1;
        for (int l = 0; l < MAXL; ++l) { offs[l] = run; run += tot[l]; if (tot[l] > 0) mx = l; }
        offs[MAXL] = run;
        g_nlv = mx;
    }
    __syncthreads();
    for (int idx = tid; idx < MAXL * B_; idx += 256) g_base[idx] += offs[idx >> 8];
    for (int l = tid; l <= MAXL; l += 256) g_off[l] = offs[l];
}

extern "C" __global__ void __launch_bounds__(128)
k_scatter()
{
    __shared__ unsigned short slv[N_];
    __shared__ int cur[MAXL];
    __shared__ int pos[N_];
    const int b = blockIdx.x, tid = threadIdx.x;
    for (int i = tid; i < N_; i += 128) slv[i] = g_lvl[b * N_ + i];
    for (int l = tid; l < MAXL; l += 128) cur[l] = g_base[l * B_ + b];
    __syncthreads();
    if (tid == 0)
        for (int i = 0; i < N_; ++i) { const int l = slv[i]; pos[i] = cur[l]++; }
    __syncthreads();
    for (int i = tid; i < N_; i += 128) g_nodes[pos[i]] = (b << 9) | i;
}

// Transpose + split Wh into mma-B fragment-packed bf16 hi/lo.
// Layout: u32 index = ((n_tile*16 + kpair)*32 + lane)*4 + ko*2 + word
//   n_tile=n>>3, kpair=k>>5, ko=(k>>4)&1, lane=((n&7)<<2)|((k>>1)&3),
//   word=(k>>3)&1, elem=k&1 (low half = even k).
extern "C" __global__ void __launch_bounds__(256)
k_split(const float* __restrict__ W_ih)
{
    const int n = blockIdx.x;
    for (int k = threadIdx.x; k < HID_; k += 256) {
        const float w = W_ih[(size_t)(IN_ + k) * HID_ + n];
        const __nv_bfloat16 h = __float2bfloat16(w);
        const __nv_bfloat16 lo = __float2bfloat16(w - __bfloat162float(h));
        const int n_tile = n >> 3, kpair = k >> 5, ko = (k >> 4) & 1;
        const int lane = ((n & 7) << 2) | ((k >> 1) & 3);
        const int word = (k >> 3) & 1, elem = k & 1;
        const size_t u32i = ((size_t)(n_tile * 16 + kpair) * 32 + lane) * 4 + ko * 2 + word;
        g_Wb_hi[u32i * 2 + elem] = h;
        g_Wb_lo[u32i * 2 + elem] = lo;
    }
}

// ============================================================================
// Grid-wide software barrier
// ============================================================================
__device__ __forceinline__ void grid_barrier(unsigned tgt, unsigned nct)
{
    __syncthreads();
    if (threadIdx.x == 0) {
        __threadfence();
        const unsigned a = atomicAdd(&g_barcnt, 1u);
        if (a == nct - 1u) {
            g_barcnt = 0u;
            __threadfence();
            atomicExch(&g_epoch, tgt);
        } else {
            unsigned e;
            do {
                asm volatile("ld.acquire.gpu.u32 %0, [%1];"
                             : "=r"(e) : "l"((unsigned*)&g_epoch) : "memory");
                if (e >= tgt) break;
                __nanosleep(64u);
            } while (true);
        }
    }
    __syncthreads();
}

// ============================================================================
// Main persistent kernel: level-parallel split-bf16 HMMA GEMM + fast tanh.
// Item: 64 nodes x 256 cols. Warp tile: 32 rows x 64 cols (2x4 warp grid).
// A (h_l+h_r gathered, hi/lo split) double-buffered in SMEM, K chunks of 128.
// B (fragment-packed Wh) loaded global->regs, coalesced LDG.128.
// ============================================================================
extern "C" __global__ void __launch_bounds__(THR_MAIN, 1)
rnn_main(const int* __restrict__ L, const int* __restrict__ R,
         const int* __restrict__ V, const float* __restrict__ W_ih,
         const float* __restrict__ b_ih)
{
    extern __shared__ char sm[];
    const uint32_t smem_base = smem_u32(sm);
    float* bih = (float*)(sm + SM_BIH);
    int*   il  = (int*)(sm + SM_META);
    int*   ir  = il + MT;
    int*   iv  = ir + MT;
    int*   io  = iv + MT;

    const int tid  = threadIdx.x;
    const int wid  = tid >> 5, lane = tid & 31;

    for (int i = tid; i < HID_; i += THR_MAIN) bih[i] = b_ih[i];

    // warp tiling: 2 row groups x 4 col groups
    const int wm  = (wid & 1) * 32;          // warp row base
    const int wgn = wid >> 1;                // col group (64 cols)
    const uint32_t a_lane = (uint32_t)((lane & 15) * A_STRIDE + (lane >> 4) * 16);
    const uint32_t aoffm0 = (uint32_t)(wm * A_STRIDE);
    const uint32_t aoffm1 = (uint32_t)((wm + 16) * A_STRIDE);

    const int nlv = g_nlv;
    const unsigned nct = gridDim.x;

    // gather mapping: row = tid>>2, k-quarter = tid&3 (32 floats)
    const int grow = tid >> 2, gks = tid & 3;

    #define GATHER(c, bf)                                                        \
    {                                                                            \
        const float4* pl = (const float4*)(g_H + (size_t)il[grow] * HID_)        \
                           + ((c) * 32 + gks * 8);                               \
        const float4* pr = (const float4*)(g_H + (size_t)ir[grow] * HID_)        \
                           + ((c) * 32 + gks * 8);                               \
        char* dh = sm + SM_AHI + (bf) * A_BUFSZ + grow * A_STRIDE + gks * 64;    \
        char* dl = sm + SM_ALO + (bf) * A_BUFSZ + grow * A_STRIDE + gks * 64;    \
        _Pragma("unroll")                                                        \
        for (int j = 0; j < 2; ++j) {                                            \
            float4 la[4], ra[4];                                                 \
            _Pragma("unroll")                                                    \
            for (int q = 0; q < 4; ++q) {                                        \
                la[q] = __ldcg(pl + j * 4 + q);                                  \
                ra[q] = __ldcg(pr + j * 4 + q);                                  \
            }                                                                    \
            uint32_t hw[8], lw[8];                                               \
            _Pragma("unroll")                                                    \
            for (int q = 0; q < 4; ++q) {                                        \
                const float s0 = la[q].x + ra[q].x, s1 = la[q].y + ra[q].y;      \
                const float s2 = la[q].z + ra[q].z, s3 = la[q].w + ra[q].w;      \
                __nv_bfloat162 h01 = __floats2bfloat162_rn(s0, s1);              \
                __nv_bfloat162 h23 = __floats2bfloat162_rn(s2, s3);              \
                hw[q * 2 + 0] = *(uint32_t*)&h01;                                \
                hw[q * 2 + 1] = *(uint32_t*)&h23;                                \
                __nv_bfloat162 l01 = __floats2bfloat162_rn(                      \
                    s0 - __low2float(h01), s1 - __high2float(h01));              \
                __nv_bfloat162 l23 = __floats2bfloat162_rn(                      \
                    s2 - __low2float(h23), s3 - __high2float(h23));              \
                lw[q * 2 + 0] = *(uint32_t*)&l01;                                \
                lw[q * 2 + 1] = *(uint32_t*)&l23;                                \
            }                                                                    \
            ((uint4*)dh)[j * 2 + 0] = make_uint4(hw[0], hw[1], hw[2], hw[3]);    \
            ((uint4*)dh)[j * 2 + 1] = make_uint4(hw[4], hw[5], hw[6], hw[7]);    \
            ((uint4*)dl)[j * 2 + 0] = make_uint4(lw[0], lw[1], lw[2], lw[3]);    \
            ((uint4*)dl)[j * 2 + 1] = make_uint4(lw[4], lw[5], lw[6], lw[7]);    \
        }                                                                        \
    }

    for (int lvl = 1; lvl <= nlv; ++lvl) {
        const int s = g_off[lvl], e = g_off[lvl + 1];
        const int items = ((e - s + MT - 1) >> 6) * 2;
        for (int w = blockIdx.x; w < items; w += (int)nct) {
            const int rt = w >> 1, hp = w & 1;
            const int t0 = s + rt * MT;
            const int ntb = hp * 32 + wgn * 8;    // global n-tile base for warp

            // ---- node metadata ----
            if (tid < MT) {
                const int gi = t0 + tid;
                if (gi < e) {
                    const int nd = g_nodes[gi];
                    const int b = nd >> 9, i = nd & (N_ - 1);
                    int l = L[b * N_ + i]; if (l < 0) l = N_;
                    int r = R[b * N_ + i]; if (r < 0) r = N_;
                    il[tid] = b * (N_ + 1) + l;
                    ir[tid] = b * (N_ + 1) + r;
                    iv[tid] = V[b * N_ + i];
                    io[tid] = b * (N_ + 1) + i;
                } else {
                    il[tid] = N_;     // zero sentinel row (b=0)
                    ir[tid] = N_;
                    iv[tid] = -1;
                }
            }
            __syncthreads();

            float acc[2][8][4];
            #pragma unroll
            for (int mt = 0; mt < 2; ++mt)
                #pragma unroll
                for (int nt = 0; nt < 8; ++nt)
                    #pragma unroll
                    for (int q = 0; q < 4; ++q) acc[mt][nt][q] = 0.0f;

            GATHER(0, 0)
            __syncthreads();

            #pragma unroll
            for (int c = 0; c < 4; ++c) {
                if (c < 3) GATHER(c + 1, (c + 1) & 1)

                const uint32_t abH = smem_base + SM_AHI + (uint32_t)((c & 1) * A_BUFSZ) + a_lane;
                const uint32_t abL = smem_base + SM_ALO + (uint32_t)((c & 1) * A_BUFSZ) + a_lane;

                #pragma unroll
                for (int kp = 0; kp < 4; ++kp) {
                    const int gkp = c * 4 + kp;
                    uint4 bh[8], bl[8];
                    {
                        const uint4* bph = (const uint4*)g_Wb_hi
                            + ((size_t)ntb * 16 + gkp) * 32 + lane;
                        const uint4* bpl = (const uint4*)g_Wb_lo
                            + ((size_t)ntb * 16 + gkp) * 32 + lane;
                        #pragma unroll
                        for (int nt = 0; nt < 8; ++nt) {
                            bh[nt] = __ldg(bph + (size_t)nt * 512);
                            bl[nt] = __ldg(bpl + (size_t)nt * 512);
                        }
                    }
                    #pragma unroll
                    for (int ks2 = 0; ks2 < 2; ++ks2) {
                        const uint32_t koff = (uint32_t)((kp * 2 + ks2) * 32);
                        uint32_t ah0[4], ah1[4], al0[4], al1[4];
                        ldsm4(ah0, abH + aoffm0 + koff);
                        ldsm4(ah1, abH + aoffm1 + koff);
                        ldsm4(al0, abL + aoffm0 + koff);
                        ldsm4(al1, abL + aoffm1 + koff);
                        // pass 0: Ahi x Bhi
                        #pragma unroll
                        for (int nt = 0; nt < 8; ++nt) {
                            const uint32_t b0 = ks2 ? bh[nt].z : bh[nt].x;
                            const uint32_t b1 = ks2 ? bh[nt].w : bh[nt].y;
                            mma16816(acc[0][nt], ah0, b0, b1);
                            mma16816(acc[1][nt], ah1, b0, b1);
                        }
                        // pass 1: Alo x Bhi
                        #pragma unroll
                        for (int nt = 0; nt < 8; ++nt) {
                            const uint32_t b0 = ks2 ? bh[nt].z : bh[nt].x;
                            const uint32_t b1 = ks2 ? bh[nt].w : bh[nt].y;
                            mma16816(acc[0][nt], al0, b0, b1);
                            mma16816(acc[1][nt], al1, b0, b1);
                        }
                        // pass 2: Ahi x Blo
                        #pragma unroll
                        for (int nt = 0; nt < 8; ++nt) {
                            const uint32_t b0 = ks2 ? bl[nt].z : bl[nt].x;
                            const uint32_t b1 = ks2 ? bl[nt].w : bl[nt].y;
                            mma16816(acc[0][nt], ah0, b0, b1);
                            mma16816(acc[1][nt], ah1, b0, b1);
                        }
                    }
                }
                __syncthreads();
            }

            // ---- epilogue: + Wx[value] + b_ih, fast tanh, store h ----
            #pragma unroll
            for (int mt = 0; mt < 2; ++mt) {
                const int r1 = wm + mt * 16 + (lane >> 2);
                const int r2 = r1 + 8;
                const int v1 = iv[r1], v2 = iv[r2];
                const int o1 = io[r1], o2 = io[r2];
                #pragma unroll
                for (int nt = 0; nt < 8; ++nt) {
                    const int gcol = hp * NHALF + wgn * 64 + nt * 8 + (lane & 3) * 2;
                    const float2 bv = *(const float2*)(bih + gcol);
                    if (v1 >= 0) {
                        const float2 wx = __ldg((const float2*)(W_ih + (size_t)v1 * HID_ + gcol));
                        float2 o;
                        o.x = ftanh(acc[mt][nt][0] + wx.x + bv.x);
                        o.y = ftanh(acc[mt][nt][1] + wx.y + bv.y);
                        *(float2*)(g_H + (size_t)o1 * HID_ + gcol) = o;
                    }
                    if (v2 >= 0) {
                        const float2 wx = __ldg((const float2*)(W_ih + (size_t)v2 * HID_ + gcol));
                        float2 o;
                        o.x = ftanh(acc[mt][nt][2] + wx.x + bv.x);
                        o.y = ftanh(acc[mt][nt][3] + wx.y + bv.y);
                        *(float2*)(g_H + (size_t)o2 * HID_ + gcol) = o;
                    }
                }
            }
            __syncthreads();   // meta/A reuse protection for next item
        }
        grid_barrier((unsigned)lvl, nct);
    }
    #undef GATHER
}

// ============================================================================
// Barrier state reset (graph-replay determinism)
// ============================================================================
extern "C" __global__ void k_reset()
{
    if (threadIdx.x == 0) { g_epoch = 0u; g_barcnt = 0u; }
}

// ============================================================================
// Output kernel: logits = h_root @ W_o + b_o, then log_softmax
// ============================================================================
extern "C" __global__ void __launch_bounds__(64)
rnn_out(const float* __restrict__ W_o,
        const float* __restrict__ b_o,
        float* __restrict__ out)
{
    __shared__ float hs[HID_];
    __shared__ float lg[OUT_];
    __shared__ float lse;
    const int b   = blockIdx.x;
    const int tid = threadIdx.x;

    const float* hrow = g_H + ((size_t)b * (N_ + 1) + (N_ - 1)) * HID_;
    #pragma unroll
    for (int j = 0; j < 2; ++j) {
        const float4 v = *(const float4*)(hrow + tid * 8 + j * 4);
        *(float4*)(hs + tid * 8 + j * 4) = v;
    }
    __syncthreads();

    if (tid < OUT_) {
        float acc = b_o[tid];
        #pragma unroll 8
        for (int k = 0; k < HID_; ++k)
            acc = fmaf(hs[k], __ldg(W_o + (size_t)k * OUT_ + tid), acc);
        lg[tid] = acc;
    }
    __syncthreads();

    if (tid == 0) {
        float m = -1e30f;
        for (int j = 0; j < OUT_; ++j) m = fmaxf(m, lg[j]);
        float ssum = 0.f;
        for (int j = 0; j < OUT_; ++j) ssum += expf(lg[j] - m);
        lse = m + logf(ssum);
    }
    __syncthreads();

    if (tid < OUT_) out[(size_t)b * OUT_ + tid] = lg[tid] - lse;
}

// ============================================================================
// Launcher: 7 graph nodes, capturable, allocation-free.
// ============================================================================
extern "C" void kernel_launch(void* const* d_in, const int* in_sizes, int n_in,
                              void* d_out, int out_size)
{
    (void)in_sizes; (void)n_in; (void)out_size;
    const int*   left  = (const int*)d_in[0];
    const int*   right = (const int*)d_in[1];
    const int*   vals  = (const int*)d_in[2];
    const float* W_ih  = (const float*)d_in[3];
    const float* b_ih  = (const float*)d_in[4];
    const float* W_o   = (const float*)d_in[5];
    const float* b_o   = (const float*)d_in[6];
    float*       out   = (float*)d_out;

    cudaFuncSetAttribute(rnn_main,
                         cudaFuncAttributeMaxDynamicSharedMemorySize, SMEM_MAIN);

    k_levels<<<B_, 128>>>(left, right);
    k_prefix<<<1, 256>>>();
    k_scatter<<<B_, 128>>>();
    k_split<<<HID_, 256>>>(W_ih);
    rnn_main<<<GRID_MAIN, THR_MAIN, SMEM_MAIN>>>(left, right, vals, W_ih, b_ih);
    k_reset<<<1, 1>>>();
    rnn_out<<<B_, 64>>>(W_o, b_o, out);
}

// round 11
// speedup vs baseline: 7.5143x; 1.0255x over previous
#include <cuda_runtime.h>
#include <cuda_bf16.h>
#include <math.h>
#include <stdint.h>

// Problem constants
#define B_    256
#define N_    512
#define HID_  512
#define IN_   57
#define OUT_  57

#define MAXL      513
#define GRID_MAIN 296            // 2 CTAs/SM x 148 SMs, co-resident (reg-limited)
#define THR_MAIN  256
#define MT        64             // nodes (rows) per item
#define NQ        128            // cols per item (quarter of N)

// ---------------- device globals ----------------
__device__ float          g_H[(size_t)B_ * (N_ + 1) * HID_];   // row N_ (b=0) = zero sentinel
__device__ __nv_bfloat16  g_Wb_hi[HID_ * HID_];   // fragment-packed Wh^T hi
__device__ __nv_bfloat16  g_Wb_lo[HID_ * HID_];   // fragment-packed Wh^T lo
__device__ unsigned short g_lvl[B_ * N_];
__device__ int            g_cntb[MAXL * B_];
__device__ int            g_base[MAXL * B_];
__device__ int            g_off[MAXL + 1];
__device__ int            g_nodes[B_ * N_];
__device__ int            g_nlv;
__device__ unsigned       g_barcnt;
__device__ unsigned       g_epoch;

// ---------------- SMEM layout ----------------
// A planes: [term hi/lo][2 buf][64 rows][136 bf16] row stride 272 B
#define A_STRIDE 272
#define A_BUFSZ  (MT * A_STRIDE)         // 17408
#define SM_AHI   0                       // 2 * 17408 = 34816
#define SM_ALO   34816                   // 2 * 17408
#define SM_BIH   69632                   // 512 f32 = 2048
#define SM_META  71680                   // il/ir/iv/io [64] each = 1024
#define SMEM_MAIN 72704                  // x2 CTAs = 145408 < 227KB/SM

// ---------------- PTX helpers (baseline ISA only) ----------------
__device__ __forceinline__ void mma16816(float* d, const uint32_t* a,
                                         uint32_t b0, uint32_t b1) {
    asm volatile(
        "mma.sync.aligned.m16n8k16.row.col.f32.bf16.bf16.f32 "
        "{%0,%1,%2,%3}, {%4,%5,%6,%7}, {%8,%9}, {%0,%1,%2,%3};\n"
        : "+f"(d[0]), "+f"(d[1]), "+f"(d[2]), "+f"(d[3])
        : "r"(a[0]), "r"(a[1]), "r"(a[2]), "r"(a[3]), "r"(b0), "r"(b1));
}
__device__ __forceinline__ void ldsm4(uint32_t* r, uint32_t a) {
    asm volatile("ldmatrix.sync.aligned.m8n8.x4.shared.b16 {%0,%1,%2,%3}, [%4];\n"
        : "=r"(r[0]), "=r"(r[1]), "=r"(r[2]), "=r"(r[3]) : "r"(a));
}
__device__ __forceinline__ uint32_t smem_u32(const void* p) {
    return (uint32_t)__cvta_generic_to_shared(p);
}

// FFMA-only tanh: tanh(x) = 1 - 2/(e^{2x}+1); exp2 via round-trick + deg-7
// Taylor; reciprocal via bit-trick seed + 3 Newton. No MUFU, no CVT.
__device__ __forceinline__ float ftanh(float x) {
    float t = fminf(fmaxf(x, -15.0f), 15.0f);
    float z = t * 2.8853900817779268f;           // 2*log2(e)*x
    float zk = z + 12582912.0f;                   // round-to-nearest-even
    float k  = zk - 12582912.0f;
    float f  = z - k;                             // f in [-0.5, 0.5]
    float p = 1.5252733814e-5f;
    p = fmaf(p, f, 1.5403530394e-4f);
    p = fmaf(p, f, 1.3333558146e-3f);
    p = fmaf(p, f, 9.6181291076e-3f);
    p = fmaf(p, f, 5.5504108664e-2f);
    p = fmaf(p, f, 2.4022650696e-1f);
    p = fmaf(p, f, 6.9314718056e-1f);
    p = fmaf(p, f, 1.0f);
    const int ib = __float_as_int(zk);
    const float sc = __int_as_float((ib + (127 - 0x4B400000)) << 23);   // 2^k
    const float E = p * sc;                       // e^{2x}
    const float d = E + 1.0f;
    float r = __int_as_float(0x7EF311C3 - __float_as_int(d));
    r = r * fmaf(-d, r, 2.0f);
    r = r * fmaf(-d, r, 2.0f);
    r = r * fmaf(-d, r, 2.0f);
    return fmaf(-2.0f, r, 1.0f);
}

// ============================================================================
// Prep kernels
// ============================================================================
extern "C" __global__ void __launch_bounds__(128)
k_levels(const int* __restrict__ L, const int* __restrict__ R)
{
    __shared__ int sli[N_], sri[N_], shist[MAXL];
    __shared__ unsigned short slv[N_];
    const int b = blockIdx.x, tid = threadIdx.x;
    for (int i = tid; i < N_; i += 128) { sli[i] = L[b * N_ + i]; sri[i] = R[b * N_ + i]; }
    for (int i = tid; i < MAXL; i += 128) shist[i] = 0;
    __syncthreads();
    if (tid == 0) {
        for (int i = 0; i < N_; ++i) {
            const int l = sli[i], r = sri[i];
            const int a = (l < 0) ? 0 : (int)slv[l];
            const int c = (r < 0) ? 0 : (int)slv[r];
            const int lv = 1 + (a > c ? a : c);
            slv[i] = (unsigned short)lv;
            shist[lv]++;
        }
    }
    __syncthreads();
    for (int i = tid; i < N_; i += 128) g_lvl[b * N_ + i] = slv[i];
    for (int l = tid; l < MAXL; l += 128) g_cntb[l * B_ + b] = shist[l];
}

extern "C" __global__ void __launch_bounds__(256)
k_prefix()
{
    __shared__ int tot[MAXL];
    __shared__ int offs[MAXL + 1];
    const int tid = threadIdx.x;
    for (int l = tid; l < MAXL; l += 256) {
        int run = 0; const int base = l * B_;
        #pragma unroll 4
        for (int b = 0; b < B_; ++b) { const int c = g_cntb[base + b]; g_base[base + b] = run; run += c; }
        tot[l] = run;
    }
    __syncthreads();
    if (tid == 0) {
        int run = 0, mx = 1;
        for (int l = 0; l < MAXL; ++l) { offs[l] = run; run += tot[l]; if (tot[l] > 0) mx = l; }
        offs[MAXL] = run;
        g_nlv = mx;
    }
    __syncthreads();
    for (int idx = tid; idx < MAXL * B_; idx += 256) g_base[idx] += offs[idx >> 8];
    for (int l = tid; l <= MAXL; l += 256) g_off[l] = offs[l];
}

extern "C" __global__ void __launch_bounds__(128)
k_scatter()
{
    __shared__ unsigned short slv[N_];
    __shared__ int cur[MAXL];
    __shared__ int pos[N_];
    const int b = blockIdx.x, tid = threadIdx.x;
    for (int i = tid; i < N_; i += 128) slv[i] = g_lvl[b * N_ + i];
    for (int l = tid; l < MAXL; l += 128) cur[l] = g_base[l * B_ + b];
    __syncthreads();
    if (tid == 0)
        for (int i = 0; i < N_; ++i) { const int l = slv[i]; pos[i] = cur[l]++; }
    __syncthreads();
    for (int i = tid; i < N_; i += 128) g_nodes[pos[i]] = (b << 9) | i;
}

// Transpose + split Wh into mma-B fragment-packed bf16 hi/lo.
// u32 index = ((n_tile*16 + kpair)*32 + lane)*4 + ko*2 + word
extern "C" __global__ void __launch_bounds__(256)
k_split(const float* __restrict__ W_ih)
{
    const int n = blockIdx.x;
    for (int k = threadIdx.x; k < HID_; k += 256) {
        const float w = W_ih[(size_t)(IN_ + k) * HID_ + n];
        const __nv_bfloat16 h = __float2bfloat16(w);
        const __nv_bfloat16 lo = __float2bfloat16(w - __bfloat162float(h));
        const int n_tile = n >> 3, kpair = k >> 5, ko = (k >> 4) & 1;
        const int lane = ((n & 7) << 2) | ((k >> 1) & 3);
        const int word = (k >> 3) & 1, elem = k & 1;
        const size_t u32i = ((size_t)(n_tile * 16 + kpair) * 32 + lane) * 4 + ko * 2 + word;
        g_Wb_hi[u32i * 2 + elem] = h;
        g_Wb_lo[u32i * 2 + elem] = lo;
    }
}

// ============================================================================
// Grid-wide software barrier
// ============================================================================
__device__ __forceinline__ void grid_barrier(unsigned tgt, unsigned nct)
{
    __syncthreads();
    if (threadIdx.x == 0) {
        __threadfence();
        const unsigned a = atomicAdd(&g_barcnt, 1u);
        if (a == nct - 1u) {
            g_barcnt = 0u;
            __threadfence();
            atomicExch(&g_epoch, tgt);
        } else {
            unsigned e;
            do {
                asm volatile("ld.acquire.gpu.u32 %0, [%1];"
                             : "=r"(e) : "l"((unsigned*)&g_epoch) : "memory");
                if (e >= tgt) break;
                __nanosleep(64u);
            } while (true);
        }
    }
    __syncthreads();
}

// ============================================================================
// Main persistent kernel: level-parallel split-bf16 HMMA GEMM + fast tanh.
// Item: 64 nodes x 128 cols (quarter-N). Warp tile: 32 rows x 32 cols
// (2x4 warp grid). A double-buffered in SMEM, K chunks of 128.
// B fragments LDG.128 from fragment-packed Wh; hi then lo reusing regs.
// 2 CTAs/SM for latency hiding and level fill.
// ============================================================================
extern "C" __global__ void __launch_bounds__(THR_MAIN, 2)
rnn_main(const int* __restrict__ L, const int* __restrict__ R,
         const int* __restrict__ V, const float* __restrict__ W_ih,
         const float* __restrict__ b_ih)
{
    extern __shared__ char sm[];
    const uint32_t smem_base = smem_u32(sm);
    float* bih = (float*)(sm + SM_BIH);
    int*   il  = (int*)(sm + SM_META);
    int*   ir  = il + MT;
    int*   iv  = ir + MT;
    int*   io  = iv + MT;

    const int tid  = threadIdx.x;
    const int wid  = tid >> 5, lane = tid & 31;

    for (int i = tid; i < HID_; i += THR_MAIN) bih[i] = b_ih[i];

    // warp tiling: 2 row groups x 4 col groups (32 cols each)
    const int wm  = (wid & 1) * 32;          // warp row base
    const int wgn = wid >> 1;                // col group (0..3)
    const uint32_t a_lane = (uint32_t)((lane & 15) * A_STRIDE + (lane >> 4) * 16);
    const uint32_t aoffm0 = (uint32_t)(wm * A_STRIDE);
    const uint32_t aoffm1 = (uint32_t)((wm + 16) * A_STRIDE);

    const int nlv = g_nlv;
    const unsigned nct = gridDim.x;

    // gather mapping: row = tid>>2, k-quarter = tid&3 (32 floats)
    const int grow = tid >> 2, gks = tid & 3;

    #define GATHER(c, bf)                                                        \
    {                                                                            \
        const float4* pl = (const float4*)(g_H + (size_t)il[grow] * HID_)        \
                           + ((c) * 32 + gks * 8);                               \
        const float4* pr = (const float4*)(g_H + (size_t)ir[grow] * HID_)        \
                           + ((c) * 32 + gks * 8);                               \
        char* dh = sm + SM_AHI + (bf) * A_BUFSZ + grow * A_STRIDE + gks * 64;    \
        char* dl = sm + SM_ALO + (bf) * A_BUFSZ + grow * A_STRIDE + gks * 64;    \
        _Pragma("unroll")                                                        \
        for (int j = 0; j < 2; ++j) {                                            \
            float4 la[4], ra[4];                                                 \
            _Pragma("unroll")                                                    \
            for (int q = 0; q < 4; ++q) {                                        \
                la[q] = __ldcg(pl + j * 4 + q);                                  \
                ra[q] = __ldcg(pr + j * 4 + q);                                  \
            }                                                                    \
            uint32_t hw[8], lw[8];                                               \
            _Pragma("unroll")                                                    \
            for (int q = 0; q < 4; ++q) {                                        \
                const float s0 = la[q].x + ra[q].x, s1 = la[q].y + ra[q].y;      \
                const float s2 = la[q].z + ra[q].z, s3 = la[q].w + ra[q].w;      \
                __nv_bfloat162 h01 = __floats2bfloat162_rn(s0, s1);              \
                __nv_bfloat162 h23 = __floats2bfloat162_rn(s2, s3);              \
                hw[q * 2 + 0] = *(uint32_t*)&h01;                                \
                hw[q * 2 + 1] = *(uint32_t*)&h23;                                \
                __nv_bfloat162 l01 = __floats2bfloat162_rn(                      \
                    s0 - __low2float(h01), s1 - __high2float(h01));              \
                __nv_bfloat162 l23 = __floats2bfloat162_rn(                      \
                    s2 - __low2float(h23), s3 - __high2float(h23));              \
                lw[q * 2 + 0] = *(uint32_t*)&l01;                                \
                lw[q * 2 + 1] = *(uint32_t*)&l23;                                \
            }                                                                    \
            ((uint4*)dh)[j * 2 + 0] = make_uint4(hw[0], hw[1], hw[2], hw[3]);    \
            ((uint4*)dh)[j * 2 + 1] = make_uint4(hw[4], hw[5], hw[6], hw[7]);    \
            ((uint4*)dl)[j * 2 + 0] = make_uint4(lw[0], lw[1], lw[2], lw[3]);    \
            ((uint4*)dl)[j * 2 + 1] = make_uint4(lw[4], lw[5], lw[6], lw[7]);    \
        }                                                                        \
    }

    for (int lvl = 1; lvl <= nlv; ++lvl) {
        const int s = g_off[lvl], e = g_off[lvl + 1];
        const int items = ((e - s + MT - 1) >> 6) * 4;
        for (int w = blockIdx.x; w < items; w += (int)nct) {
            const int rt = w >> 2, hp = w & 3;            // row tile / col quarter
            const int t0 = s + rt * MT;
            const int ntb = hp * 16 + wgn * 4;            // global n-tile base

            // ---- node metadata ----
            if (tid < MT) {
                const int gi = t0 + tid;
                if (gi < e) {
                    const int nd = g_nodes[gi];
                    const int b = nd >> 9, i = nd & (N_ - 1);
                    int l = L[b * N_ + i]; if (l < 0) l = N_;
                    int r = R[b * N_ + i]; if (r < 0) r = N_;
                    il[tid] = b * (N_ + 1) + l;
                    ir[tid] = b * (N_ + 1) + r;
                    iv[tid] = V[b * N_ + i];
                    io[tid] = b * (N_ + 1) + i;
                } else {
                    il[tid] = N_;     // zero sentinel row (b=0)
                    ir[tid] = N_;
                    iv[tid] = -1;
                }
            }
            __syncthreads();

            float acc[2][4][4];
            #pragma unroll
            for (int mt = 0; mt < 2; ++mt)
                #pragma unroll
                for (int nt = 0; nt < 4; ++nt)
                    #pragma unroll
                    for (int q = 0; q < 4; ++q) acc[mt][nt][q] = 0.0f;

            GATHER(0, 0)
            __syncthreads();

            #pragma unroll
            for (int c = 0; c < 4; ++c) {
                if (c < 3) GATHER(c + 1, (c + 1) & 1)

                const uint32_t abH = smem_base + SM_AHI + (uint32_t)((c & 1) * A_BUFSZ) + a_lane;
                const uint32_t abL = smem_base + SM_ALO + (uint32_t)((c & 1) * A_BUFSZ) + a_lane;

                #pragma unroll
                for (int kp = 0; kp < 4; ++kp) {
                    const int gkp = c * 4 + kp;
                    // A fragments for both k16 halves (kept for all 3 passes)
                    uint32_t ah[2][2][4], al[2][2][4];   // [ks2][mtile][4]
                    #pragma unroll
                    for (int ks2 = 0; ks2 < 2; ++ks2) {
                        const uint32_t koff = (uint32_t)((kp * 2 + ks2) * 32);
                        ldsm4(ah[ks2][0], abH + aoffm0 + koff);
                        ldsm4(ah[ks2][1], abH + aoffm1 + koff);
                        ldsm4(al[ks2][0], abL + aoffm0 + koff);
                        ldsm4(al[ks2][1], abL + aoffm1 + koff);
                    }
                    // B hi fragments -> passes 0 (Ahi) and 1 (Alo)
                    uint4 bfr[4];
                    {
                        const uint4* bph = (const uint4*)g_Wb_hi
                            + ((size_t)ntb * 16 + gkp) * 32 + lane;
                        #pragma unroll
                        for (int nt = 0; nt < 4; ++nt)
                            bfr[nt] = __ldg(bph + (size_t)nt * 512);
                    }
                    #pragma unroll
                    for (int ks2 = 0; ks2 < 2; ++ks2)
                        #pragma unroll
                        for (int nt = 0; nt < 4; ++nt) {
                            const uint32_t b0 = ks2 ? bfr[nt].z : bfr[nt].x;
                            const uint32_t b1 = ks2 ? bfr[nt].w : bfr[nt].y;
                            mma16816(acc[0][nt], ah[ks2][0], b0, b1);
                            mma16816(acc[1][nt], ah[ks2][1], b0, b1);
                            mma16816(acc[0][nt], al[ks2][0], b0, b1);
                            mma16816(acc[1][nt], al[ks2][1], b0, b1);
                        }
                    // B lo fragments (reuse regs) -> pass 2 (Ahi x Blo)
                    {
                        const uint4* bpl = (const uint4*)g_Wb_lo
                            + ((size_t)ntb * 16 + gkp) * 32 + lane;
                        #pragma unroll
                        for (int nt = 0; nt < 4; ++nt)
                            bfr[nt] = __ldg(bpl + (size_t)nt * 512);
                    }
                    #pragma unroll
                    for (int ks2 = 0; ks2 < 2; ++ks2)
                        #pragma unroll
                        for (int nt = 0; nt < 4; ++nt) {
                            const uint32_t b0 = ks2 ? bfr[nt].z : bfr[nt].x;
                            const uint32_t b1 = ks2 ? bfr[nt].w : bfr[nt].y;
                            mma16816(acc[0][nt], ah[ks2][0], b0, b1);
                            mma16816(acc[1][nt], ah[ks2][1], b0, b1);
                        }
                }
                __syncthreads();
            }

            // ---- epilogue: + Wx[value] + b_ih, fast tanh, store h ----
            #pragma unroll
            for (int mt = 0; mt < 2; ++mt) {
                const int r1 = wm + mt * 16 + (lane >> 2);
                const int r2 = r1 + 8;
                const int v1 = iv[r1], v2 = iv[r2];
                const int o1 = io[r1], o2 = io[r2];
                #pragma unroll
                for (int nt = 0; nt < 4; ++nt) {
                    const int gcol = hp * NQ + wgn * 32 + nt * 8 + (lane & 3) * 2;
                    const float2 bv = *(const float2*)(bih + gcol);
                    if (v1 >= 0) {
                        const float2 wx = __ldg((const float2*)(W_ih + (size_t)v1 * HID_ + gcol));
                        float2 o;
                        o.x = ftanh(acc[mt][nt][0] + wx.x + bv.x);
                        o.y = ftanh(acc[mt][nt][1] + wx.y + bv.y);
                        *(float2*)(g_H + (size_t)o1 * HID_ + gcol) = o;
                    }
                    if (v2 >= 0) {
                        const float2 wx = __ldg((const float2*)(W_ih + (size_t)v2 * HID_ + gcol));
                        float2 o;
                        o.x = ftanh(acc[mt][nt][2] + wx.x + bv.x);
                        o.y = ftanh(acc[mt][nt][3] + wx.y + bv.y);
                        *(float2*)(g_H + (size_t)o2 * HID_ + gcol) = o;
                    }
                }
            }
            __syncthreads();   // meta/A reuse protection for next item
        }
        grid_barrier((unsigned)lvl, nct);
    }
    #undef GATHER
}

// ============================================================================
// Barrier state reset (graph-replay determinism)
// ============================================================================
extern "C" __global__ void k_reset()
{
    if (threadIdx.x == 0) { g_epoch = 0u; g_barcnt = 0u; }
}

// ============================================================================
// Output kernel: logits = h_root @ W_o + b_o, then log_softmax
// ============================================================================
extern "C" __global__ void __launch_bounds__(64)
rnn_out(const float* __restrict__ W_o,
        const float* __restrict__ b_o,
        float* __restrict__ out)
{
    __shared__ float hs[HID_];
    __shared__ float lg[OUT_];
    __shared__ float lse;
    const int b   = blockIdx.x;
    const int tid = threadIdx.x;

    const float* hrow = g_H + ((size_t)b * (N_ + 1) + (N_ - 1)) * HID_;
    #pragma unroll
    for (int j = 0; j < 2; ++j) {
        const float4 v = *(const float4*)(hrow + tid * 8 + j * 4);
        *(float4*)(hs + tid * 8 + j * 4) = v;
    }
    __syncthreads();

    if (tid < OUT_) {
        float acc = b_o[tid];
        #pragma unroll 8
        for (int k = 0; k < HID_; ++k)
            acc = fmaf(hs[k], __ldg(W_o + (size_t)k * OUT_ + tid), acc);
        lg[tid] = acc;
    }
    __syncthreads();

    if (tid == 0) {
        float m = -1e30f;
        for (int j = 0; j < OUT_; ++j) m = fmaxf(m, lg[j]);
        float ssum = 0.f;
        for (int j = 0; j < OUT_; ++j) ssum += expf(lg[j] - m);
        lse = m + logf(ssum);
    }
    __syncthreads();

    if (tid < OUT_) out[(size_t)b * OUT_ + tid] = lg[tid] - lse;
}

// ============================================================================
// Launcher: 7 graph nodes, capturable, allocation-free.
// ============================================================================
extern "C" void kernel_launch(void* const* d_in, const int* in_sizes, int n_in,
                              void* d_out, int out_size)
{
    (void)in_sizes; (void)n_in; (void)out_size;
    const int*   left  = (const int*)d_in[0];
    const int*   right = (const int*)d_in[1];
    const int*   vals  = (const int*)d_in[2];
    const float* W_ih  = (const float*)d_in[3];
    const float* b_ih  = (const float*)d_in[4];
    const float* W_o   = (const float*)d_in[5];
    const float* b_o   = (const float*)d_in[6];
    float*       out   = (float*)d_out;

    cudaFuncSetAttribute(rnn_main,
                         cudaFuncAttributeMaxDynamicSharedMemorySize, SMEM_MAIN);

    k_levels<<<B_, 128>>>(left, right);
    k_prefix<<<1, 256>>>();
    k_scatter<<<B_, 128>>>();
    k_split<<<HID_, 256>>>(W_ih);
    rnn_main<<<GRID_MAIN, THR_MAIN, SMEM_MAIN>>>(left, right, vals, W_ih, b_ih);
    k_reset<<<1, 1>>>();
    rnn_out<<<B_, 64>>>(W_o, b_o, out);
}

// round 12
// speedup vs baseline: 8.3322x; 1.1088x over previous
#include <cuda_runtime.h>
#include <cuda_fp16.h>
#include <math.h>
#include <stdint.h>

// Problem constants
#define B_    256
#define N_    512
#define HID_  512
#define IN_   57
#define OUT_  57

#define MAXL      513
#define GRID_MAIN 296            // 2 CTAs/SM x 148 SMs, co-resident
#define THR_MAIN  256
#define MT        64             // nodes (rows) per item
#define NQ        128            // cols per item (quarter of N)

// ---------------- device globals ----------------
__device__ float          g_H[(size_t)B_ * (N_ + 1) * HID_];   // row N_ (b=0) = zero sentinel
__device__ __half         g_Wb_hi[HID_ * HID_];   // fragment-packed Wh^T hi (fp16)
__device__ __half         g_Wb_lo[HID_ * HID_];   // fragment-packed Wh^T lo (fp16 residual)
__device__ unsigned short g_lvl[B_ * N_];
__device__ int            g_cntb[MAXL * B_];
__device__ int            g_base[MAXL * B_];
__device__ int            g_off[MAXL + 1];
__device__ int            g_nodes[B_ * N_];
__device__ int            g_nlv;
__device__ unsigned       g_barcnt;
__device__ unsigned       g_epoch;

// ---------------- SMEM layout ----------------
// A plane (single, fp16): [2 buf][64 rows][136 fp16] row stride 272 B
#define A_STRIDE 272
#define A_BUFSZ  (MT * A_STRIDE)         // 17408
#define SM_A     0                       // 2 * 17408 = 34816
#define SM_BIH   34816                   // 512 f32 = 2048
#define SM_META  36864                   // il/ir/iv/io [64] each = 1024
#define SMEM_MAIN 37888                  // x2 CTAs = 75776 B/SM

// ---------------- PTX helpers (baseline ISA only) ----------------
__device__ __forceinline__ void mma16816(float* d, const uint32_t* a,
                                         uint32_t b0, uint32_t b1) {
    asm volatile(
        "mma.sync.aligned.m16n8k16.row.col.f32.f16.f16.f32 "
        "{%0,%1,%2,%3}, {%4,%5,%6,%7}, {%8,%9}, {%0,%1,%2,%3};\n"
        : "+f"(d[0]), "+f"(d[1]), "+f"(d[2]), "+f"(d[3])
        : "r"(a[0]), "r"(a[1]), "r"(a[2]), "r"(a[3]), "r"(b0), "r"(b1));
}
__device__ __forceinline__ void ldsm4(uint32_t* r, uint32_t a) {
    asm volatile("ldmatrix.sync.aligned.m8n8.x4.shared.b16 {%0,%1,%2,%3}, [%4];\n"
        : "=r"(r[0]), "=r"(r[1]), "=r"(r[2]), "=r"(r[3]) : "r"(a));
}
__device__ __forceinline__ uint32_t smem_u32(const void* p) {
    return (uint32_t)__cvta_generic_to_shared(p);
}

// FFMA-only tanh: tanh(x) = 1 - 2/(e^{2x}+1); exp2 via round-trick + deg-7
// Taylor; reciprocal via bit-trick seed + 3 Newton. No MUFU, no CVT.
__device__ __forceinline__ float ftanh(float x) {
    float t = fminf(fmaxf(x, -15.0f), 15.0f);
    float z = t * 2.8853900817779268f;           // 2*log2(e)*x
    float zk = z + 12582912.0f;                   // round-to-nearest-even
    float k  = zk - 12582912.0f;
    float f  = z - k;                             // f in [-0.5, 0.5]
    float p = 1.5252733814e-5f;
    p = fmaf(p, f, 1.5403530394e-4f);
    p = fmaf(p, f, 1.3333558146e-3f);
    p = fmaf(p, f, 9.6181291076e-3f);
    p = fmaf(p, f, 5.5504108664e-2f);
    p = fmaf(p, f, 2.4022650696e-1f);
    p = fmaf(p, f, 6.9314718056e-1f);
    p = fmaf(p, f, 1.0f);
    const int ib = __float_as_int(zk);
    const float sc = __int_as_float((ib + (127 - 0x4B400000)) << 23);   // 2^k
    const float E = p * sc;                       // e^{2x}
    const float d = E + 1.0f;
    float r = __int_as_float(0x7EF311C3 - __float_as_int(d));
    r = r * fmaf(-d, r, 2.0f);
    r = r * fmaf(-d, r, 2.0f);
    r = r * fmaf(-d, r, 2.0f);
    return fmaf(-2.0f, r, 1.0f);
}

// ============================================================================
// Prep kernels
// ============================================================================
extern "C" __global__ void __launch_bounds__(128)
k_levels(const int* __restrict__ L, const int* __restrict__ R)
{
    __shared__ int sli[N_], sri[N_], shist[MAXL];
    __shared__ unsigned short slv[N_];
    const int b = blockIdx.x, tid = threadIdx.x;
    for (int i = tid; i < N_; i += 128) { sli[i] = L[b * N_ + i]; sri[i] = R[b * N_ + i]; }
    for (int i = tid; i < MAXL; i += 128) shist[i] = 0;
    __syncthreads();
    if (tid == 0) {
        for (int i = 0; i < N_; ++i) {
            const int l = sli[i], r = sri[i];
            const int a = (l < 0) ? 0 : (int)slv[l];
            const int c = (r < 0) ? 0 : (int)slv[r];
            const int lv = 1 + (a > c ? a : c);
            slv[i] = (unsigned short)lv;
            shist[lv]++;
        }
    }
    __syncthreads();
    for (int i = tid; i < N_; i += 128) g_lvl[b * N_ + i] = slv[i];
    for (int l = tid; l < MAXL; l += 128) g_cntb[l * B_ + b] = shist[l];
}

extern "C" __global__ void __launch_bounds__(256)
k_prefix()
{
    __shared__ int tot[MAXL];
    __shared__ int offs[MAXL + 1];
    const int tid = threadIdx.x;
    for (int l = tid; l < MAXL; l += 256) {
        int run = 0; const int base = l * B_;
        #pragma unroll 4
        for (int b = 0; b < B_; ++b) { const int c = g_cntb[base + b]; g_base[base + b] = run; run += c; }
        tot[l] = run;
    }
    __syncthreads();
    if (tid == 0) {
        int run = 0, mx = 1;
        for (int l = 0; l < MAXL; ++l) { offs[l] = run; run += tot[l]; if (tot[l] > 0) mx = l; }
        offs[MAXL] = run;
        g_nlv = mx;
    }
    __syncthreads();
    for (int idx = tid; idx < MAXL * B_; idx += 256) g_base[idx] += offs[idx >> 8];
    for (int l = tid; l <= MAXL; l += 256) g_off[l] = offs[l];
}

// counting-sort scatter + Wh transpose/split (merged: keeps graph at 6 nodes)
extern "C" __global__ void __launch_bounds__(128)
k_scatter(const float* __restrict__ W_ih)
{
    __shared__ unsigned short slv[N_];
    __shared__ int cur[MAXL];
    __shared__ int pos[N_];
    const int b = blockIdx.x, tid = threadIdx.x;
    for (int i = tid; i < N_; i += 128) slv[i] = g_lvl[b * N_ + i];
    for (int l = tid; l < MAXL; l += 128) cur[l] = g_base[l * B_ + b];
    __syncthreads();
    if (tid == 0)
        for (int i = 0; i < N_; ++i) { const int l = slv[i]; pos[i] = cur[l]++; }
    __syncthreads();
    for (int i = tid; i < N_; i += 128) g_nodes[pos[i]] = (b << 9) | i;

    // ---- Wh transpose + fp16 hi/lo split, fragment-packed for mma.B ----
    // u32 index = ((n_tile*16 + kpair)*32 + lane)*4 + ko*2 + word
    for (int t = tid; t < 2 * HID_; t += 128) {
        const int n = 2 * b + (t >> 9);          // 2 n-rows per block
        const int k = t & (HID_ - 1);
        const float w = W_ih[(size_t)(IN_ + k) * HID_ + n];
        const __half h = __float2half_rn(w);
        const __half lo = __float2half_rn(w - __half2float(h));
        const int n_tile = n >> 3, kpair = k >> 5, ko = (k >> 4) & 1;
        const int lane = ((n & 7) << 2) | ((k >> 1) & 3);
        const int word = (k >> 3) & 1, elem = k & 1;
        const size_t u32i = ((size_t)(n_tile * 16 + kpair) * 32 + lane) * 4 + ko * 2 + word;
        g_Wb_hi[u32i * 2 + elem] = h;
        g_Wb_lo[u32i * 2 + elem] = lo;
    }
}

// ============================================================================
// Grid-wide software barrier
// ============================================================================
__device__ __forceinline__ void grid_barrier(unsigned tgt, unsigned nct)
{
    __syncthreads();
    if (threadIdx.x == 0) {
        __threadfence();
        const unsigned a = atomicAdd(&g_barcnt, 1u);
        if (a == nct - 1u) {
            g_barcnt = 0u;
            __threadfence();
            atomicExch(&g_epoch, tgt);
        } else {
            unsigned e;
            do {
                asm volatile("ld.acquire.gpu.u32 %0, [%1];"
                             : "=r"(e) : "l"((unsigned*)&g_epoch) : "memory");
                if (e >= tgt) break;
                __nanosleep(64u);
            } while (true);
        }
    }
    __syncthreads();
}

// ============================================================================
// Main persistent kernel: level-parallel fp16 2-pass HMMA GEMM + fast tanh.
// Item: 64 nodes x 128 cols. Warp tile: 32 rows x 32 cols (2x4 warp grid).
// A = fp16(h_l + h_r) single plane, double-buffered SMEM, K chunks of 128.
// W split fp16 hi+lo (exact to 2^-24): D = A*Whi + A*Wlo  (2 HMMA passes).
// Only error source: A's fp16 rounding (~2^-12) -> rel_err ~1e-5..1e-4.
// ============================================================================
extern "C" __global__ void __launch_bounds__(THR_MAIN, 2)
rnn_main(const int* __restrict__ L, const int* __restrict__ R,
         const int* __restrict__ V, const float* __restrict__ W_ih,
         const float* __restrict__ b_ih)
{
    extern __shared__ char sm[];
    const uint32_t smem_base = smem_u32(sm);
    float* bih = (float*)(sm + SM_BIH);
    int*   il  = (int*)(sm + SM_META);
    int*   ir  = il + MT;
    int*   iv  = ir + MT;
    int*   io  = iv + MT;

    const int tid  = threadIdx.x;
    const int wid  = tid >> 5, lane = tid & 31;

    for (int i = tid; i < HID_; i += THR_MAIN) bih[i] = b_ih[i];

    // warp tiling: 2 row groups x 4 col groups (32 cols each)
    const int wm  = (wid & 1) * 32;          // warp row base
    const int wgn = wid >> 1;                // col group (0..3)
    const uint32_t a_lane = (uint32_t)((lane & 15) * A_STRIDE + (lane >> 4) * 16);
    const uint32_t aoffm0 = (uint32_t)(wm * A_STRIDE);
    const uint32_t aoffm1 = (uint32_t)((wm + 16) * A_STRIDE);

    const int nlv = g_nlv;
    const unsigned nct = gridDim.x;

    // gather mapping: row = tid>>2, k-quarter = tid&3 (32 floats)
    const int grow = tid >> 2, gks = tid & 3;

    #define GATHER(c, bf)                                                        \
    {                                                                            \
        const float4* pl = (const float4*)(g_H + (size_t)il[grow] * HID_)        \
                           + ((c) * 32 + gks * 8);                               \
        const float4* pr = (const float4*)(g_H + (size_t)ir[grow] * HID_)        \
                           + ((c) * 32 + gks * 8);                               \
        char* dh = sm + SM_A + (bf) * A_BUFSZ + grow * A_STRIDE + gks * 64;      \
        _Pragma("unroll")                                                        \
        for (int j = 0; j < 2; ++j) {                                            \
            float4 la[4], ra[4];                                                 \
            _Pragma("unroll")                                                    \
            for (int q = 0; q < 4; ++q) {                                        \
                la[q] = __ldcg(pl + j * 4 + q);                                  \
                ra[q] = __ldcg(pr + j * 4 + q);                                  \
            }                                                                    \
            uint32_t hw[8];                                                      \
            _Pragma("unroll")                                                    \
            for (int q = 0; q < 4; ++q) {                                        \
                const __half2 h01 = __floats2half2_rn(la[q].x + ra[q].x,         \
                                                      la[q].y + ra[q].y);        \
                const __half2 h23 = __floats2half2_rn(la[q].z + ra[q].z,         \
                                                      la[q].w + ra[q].w);        \
                hw[q * 2 + 0] = *(const uint32_t*)&h01;                          \
                hw[q * 2 + 1] = *(const uint32_t*)&h23;                          \
            }                                                                    \
            ((uint4*)dh)[j * 2 + 0] = make_uint4(hw[0], hw[1], hw[2], hw[3]);    \
            ((uint4*)dh)[j * 2 + 1] = make_uint4(hw[4], hw[5], hw[6], hw[7]);    \
        }                                                                        \
    }

    for (int lvl = 1; lvl <= nlv; ++lvl) {
        const int s = g_off[lvl], e = g_off[lvl + 1];
        const int items = ((e - s + MT - 1) >> 6) * 4;
        for (int w = blockIdx.x; w < items; w += (int)nct) {
            const int rt = w >> 2, hp = w & 3;            // row tile / col quarter
            const int t0 = s + rt * MT;
            const int ntb = hp * 16 + wgn * 4;            // global n-tile base

            // ---- node metadata ----
            if (tid < MT) {
                const int gi = t0 + tid;
                if (gi < e) {
                    const int nd = g_nodes[gi];
                    const int b = nd >> 9, i = nd & (N_ - 1);
                    int l = L[b * N_ + i]; if (l < 0) l = N_;
                    int r = R[b * N_ + i]; if (r < 0) r = N_;
                    il[tid] = b * (N_ + 1) + l;
                    ir[tid] = b * (N_ + 1) + r;
                    iv[tid] = V[b * N_ + i];
                    io[tid] = b * (N_ + 1) + i;
                } else {
                    il[tid] = N_;     // zero sentinel row (b=0)
                    ir[tid] = N_;
                    iv[tid] = -1;
                }
            }
            __syncthreads();

            float acc[2][4][4];
            #pragma unroll
            for (int mt = 0; mt < 2; ++mt)
                #pragma unroll
                for (int nt = 0; nt < 4; ++nt)
                    #pragma unroll
                    for (int q = 0; q < 4; ++q) acc[mt][nt][q] = 0.0f;

            GATHER(0, 0)
            __syncthreads();

            #pragma unroll
            for (int c = 0; c < 4; ++c) {
                if (c < 3) GATHER(c + 1, (c + 1) & 1)

                const uint32_t abA = smem_base + SM_A + (uint32_t)((c & 1) * A_BUFSZ) + a_lane;

                #pragma unroll
                for (int kp = 0; kp < 4; ++kp) {
                    const int gkp = c * 4 + kp;
                    // A fragments for both k16 halves (single fp16 plane)
                    uint32_t ah[2][2][4];                // [ks2][mtile][4]
                    #pragma unroll
                    for (int ks2 = 0; ks2 < 2; ++ks2) {
                        const uint32_t koff = (uint32_t)((kp * 2 + ks2) * 32);
                        ldsm4(ah[ks2][0], abA + aoffm0 + koff);
                        ldsm4(ah[ks2][1], abA + aoffm1 + koff);
                    }
                    // pass 0: A x Whi
                    uint4 bfr[4];
                    {
                        const uint4* bph = (const uint4*)g_Wb_hi
                            + ((size_t)ntb * 16 + gkp) * 32 + lane;
                        #pragma unroll
                        for (int nt = 0; nt < 4; ++nt)
                            bfr[nt] = __ldg(bph + (size_t)nt * 512);
                    }
                    #pragma unroll
                    for (int ks2 = 0; ks2 < 2; ++ks2)
                        #pragma unroll
                        for (int nt = 0; nt < 4; ++nt) {
                            const uint32_t b0 = ks2 ? bfr[nt].z : bfr[nt].x;
                            const uint32_t b1 = ks2 ? bfr[nt].w : bfr[nt].y;
                            mma16816(acc[0][nt], ah[ks2][0], b0, b1);
                            mma16816(acc[1][nt], ah[ks2][1], b0, b1);
                        }
                    // pass 1: A x Wlo (reuse B regs)
                    {
                        const uint4* bpl = (const uint4*)g_Wb_lo
                            + ((size_t)ntb * 16 + gkp) * 32 + lane;
                        #pragma unroll
                        for (int nt = 0; nt < 4; ++nt)
                            bfr[nt] = __ldg(bpl + (size_t)nt * 512);
                    }
                    #pragma unroll
                    for (int ks2 = 0; ks2 < 2; ++ks2)
                        #pragma unroll
                        for (int nt = 0; nt < 4; ++nt) {
                            const uint32_t b0 = ks2 ? bfr[nt].z : bfr[nt].x;
                            const uint32_t b1 = ks2 ? bfr[nt].w : bfr[nt].y;
                            mma16816(acc[0][nt], ah[ks2][0], b0, b1);
                            mma16816(acc[1][nt], ah[ks2][1], b0, b1);
                        }
                }
                __syncthreads();
            }

            // ---- epilogue: + Wx[value] + b_ih, fast tanh, store h ----
            #pragma unroll
            for (int mt = 0; mt < 2; ++mt) {
                const int r1 = wm + mt * 16 + (lane >> 2);
                const int r2 = r1 + 8;
                const int v1 = iv[r1], v2 = iv[r2];
                const int o1 = io[r1], o2 = io[r2];
                #pragma unroll
                for (int nt = 0; nt < 4; ++nt) {
                    const int gcol = hp * NQ + wgn * 32 + nt * 8 + (lane & 3) * 2;
                    const float2 bv = *(const float2*)(bih + gcol);
                    if (v1 >= 0) {
                        const float2 wx = __ldg((const float2*)(W_ih + (size_t)v1 * HID_ + gcol));
                        float2 o;
                        o.x = ftanh(acc[mt][nt][0] + wx.x + bv.x);
                        o.y = ftanh(acc[mt][nt][1] + wx.y + bv.y);
                        *(float2*)(g_H + (size_t)o1 * HID_ + gcol) = o;
                    }
                    if (v2 >= 0) {
                        const float2 wx = __ldg((const float2*)(W_ih + (size_t)v2 * HID_ + gcol));
                        float2 o;
                        o.x = ftanh(acc[mt][nt][2] + wx.x + bv.x);
                        o.y = ftanh(acc[mt][nt][3] + wx.y + bv.y);
                        *(float2*)(g_H + (size_t)o2 * HID_ + gcol) = o;
                    }
                }
            }
            __syncthreads();   // meta/A reuse protection for next item
        }
        grid_barrier((unsigned)lvl, nct);
    }
    #undef GATHER
}

// ============================================================================
// Barrier state reset (graph-replay determinism)
// ============================================================================
extern "C" __global__ void k_reset()
{
    if (threadIdx.x == 0) { g_epoch = 0u; g_barcnt = 0u; }
}

// ============================================================================
// Output kernel: logits = h_root @ W_o + b_o, then log_softmax
// ============================================================================
extern "C" __global__ void __launch_bounds__(64)
rnn_out(const float* __restrict__ W_o,
        const float* __restrict__ b_o,
        float* __restrict__ out)
{
    __shared__ float hs[HID_];
    __shared__ float lg[OUT_];
    __shared__ float lse;
    const int b   = blockIdx.x;
    const int tid = threadIdx.x;

    const float* hrow = g_H + ((size_t)b * (N_ + 1) + (N_ - 1)) * HID_;
    #pragma unroll
    for (int j = 0; j < 2; ++j) {
        const float4 v = *(const float4*)(hrow + tid * 8 + j * 4);
        *(float4*)(hs + tid * 8 + j * 4) = v;
    }
    __syncthreads();

    if (tid < OUT_) {
        float acc = b_o[tid];
        #pragma unroll 8
        for (int k = 0; k < HID_; ++k)
            acc = fmaf(hs[k], __ldg(W_o + (size_t)k * OUT_ + tid), acc);
        lg[tid] = acc;
    }
    __syncthreads();

    if (tid == 0) {
        float m = -1e30f;
        for (int j = 0; j < OUT_; ++j) m = fmaxf(m, lg[j]);
        float ssum = 0.f;
        for (int j = 0; j < OUT_; ++j) ssum += expf(lg[j] - m);
        lse = m + logf(ssum);
    }
    __syncthreads();

    if (tid < OUT_) out[(size_t)b * OUT_ + tid] = lg[tid] - lse;
}

// ============================================================================
// Launcher: 6 graph nodes, capturable, allocation-free.
// ============================================================================
extern "C" void kernel_launch(void* const* d_in, const int* in_sizes, int n_in,
                              void* d_out, int out_size)
{
    (void)in_sizes; (void)n_in; (void)out_size;
    const int*   left  = (const int*)d_in[0];
    const int*   right = (const int*)d_in[1];
    const int*   vals  = (const int*)d_in[2];
    const float* W_ih  = (const float*)d_in[3];
    const float* b_ih  = (const float*)d_in[4];
    const float* W_o   = (const float*)d_in[5];
    const float* b_o   = (const float*)d_in[6];
    float*       out   = (float*)d_out;

    cudaFuncSetAttribute(rnn_main,
                         cudaFuncAttributeMaxDynamicSharedMemorySize, SMEM_MAIN);

    k_levels<<<B_, 128>>>(left, right);
    k_prefix<<<1, 256>>>();
    k_scatter<<<B_, 128>>>(W_ih);
    rnn_main<<<GRID_MAIN, THR_MAIN, SMEM_MAIN>>>(left, right, vals, W_ih, b_ih);
    k_reset<<<1, 1>>>();
    rnn_out<<<B_, 64>>>(W_o, b_o, out);
}

// round 14
// speedup vs baseline: 8.9136x; 1.0698x over previous
#include <cuda_runtime.h>
#include <cuda_fp16.h>
#include <math.h>
#include <stdint.h>

// Problem constants
#define B_    256
#define N_    512
#define HID_  512
#define IN_   57
#define OUT_  57

#define MAXL      513
#define GRID_MAIN 296            // 2 CTAs/SM x 148 SMs, co-resident
#define THR_MAIN  256
#define MT        64             // nodes (rows) per item
#define NQ        128            // cols per item (quarter of N)

// ---------------- device globals ----------------
__device__ float          g_H[(size_t)B_ * (N_ + 1) * HID_];   // row N_ (b=0) = zero sentinel
__device__ __half         g_Wb[HID_ * HID_];      // fragment-packed Wh^T (fp16)
__device__ unsigned short g_lvl[B_ * N_];
__device__ int            g_cntb[MAXL * B_];
__device__ int            g_base[MAXL * B_];
__device__ int            g_off[MAXL + 1];
__device__ int            g_nodes[B_ * N_];
__device__ int            g_nlv;
__device__ unsigned       g_barcnt;
__device__ unsigned       g_epoch;

// ---------------- SMEM layout ----------------
// A plane (single, fp16): [2 buf][64 rows][136 fp16] row stride 272 B
#define A_STRIDE 272
#define A_BUFSZ  (MT * A_STRIDE)         // 17408
#define SM_A     0                       // 2 * 17408 = 34816
#define SM_BIH   34816                   // 512 f32 = 2048
#define SM_META  36864                   // il/ir/iv/io [64] each = 1024
#define SMEM_MAIN 37888                  // x2 CTAs = 75776 B/SM

// ---------------- PTX helpers (baseline ISA only) ----------------
__device__ __forceinline__ void mma16816(float* d, const uint32_t* a,
                                         uint32_t b0, uint32_t b1) {
    asm volatile(
        "mma.sync.aligned.m16n8k16.row.col.f32.f16.f16.f32 "
        "{%0,%1,%2,%3}, {%4,%5,%6,%7}, {%8,%9}, {%0,%1,%2,%3};\n"
        : "+f"(d[0]), "+f"(d[1]), "+f"(d[2]), "+f"(d[3])
        : "r"(a[0]), "r"(a[1]), "r"(a[2]), "r"(a[3]), "r"(b0), "r"(b1));
}
__device__ __forceinline__ void ldsm4(uint32_t* r, uint32_t a) {
    asm volatile("ldmatrix.sync.aligned.m8n8.x4.shared.b16 {%0,%1,%2,%3}, [%4];\n"
        : "=r"(r[0]), "=r"(r[1]), "=r"(r[2]), "=r"(r[3]) : "r"(a));
}
__device__ __forceinline__ uint32_t smem_u32(const void* p) {
    return (uint32_t)__cvta_generic_to_shared(p);
}

// FFMA-only tanh: tanh(x) = 1 - 2/(e^{2x}+1); exp2 via round-trick + deg-7
// Taylor; reciprocal via bit-trick seed + 3 Newton. No MUFU, no CVT.
__device__ __forceinline__ float ftanh(float x) {
    float t = fminf(fmaxf(x, -15.0f), 15.0f);
    float z = t * 2.8853900817779268f;           // 2*log2(e)*x
    float zk = z + 12582912.0f;                   // round-to-nearest-even
    float k  = zk - 12582912.0f;
    float f  = z - k;                             // f in [-0.5, 0.5]
    float p = 1.5252733814e-5f;
    p = fmaf(p, f, 1.5403530394e-4f);
    p = fmaf(p, f, 1.3333558146e-3f);
    p = fmaf(p, f, 9.6181291076e-3f);
    p = fmaf(p, f, 5.5504108664e-2f);
    p = fmaf(p, f, 2.4022650696e-1f);
    p = fmaf(p, f, 6.9314718056e-1f);
    p = fmaf(p, f, 1.0f);
    const int ib = __float_as_int(zk);
    const float sc = __int_as_float((ib + (127 - 0x4B400000)) << 23);   // 2^k
    const float E = p * sc;                       // e^{2x}
    const float d = E + 1.0f;
    float r = __int_as_float(0x7EF311C3 - __float_as_int(d));
    r = r * fmaf(-d, r, 2.0f);
    r = r * fmaf(-d, r, 2.0f);
    r = r * fmaf(-d, r, 2.0f);
    return fmaf(-2.0f, r, 1.0f);
}

// ============================================================================
// Prep kernels
// ============================================================================
extern "C" __global__ void __launch_bounds__(128)
k_levels(const int* __restrict__ L, const int* __restrict__ R)
{
    __shared__ int sli[N_], sri[N_], shist[MAXL];
    __shared__ unsigned short slv[N_];
    const int b = blockIdx.x, tid = threadIdx.x;
    for (int i = tid; i < N_; i += 128) { sli[i] = L[b * N_ + i]; sri[i] = R[b * N_ + i]; }
    for (int i = tid; i < MAXL; i += 128) shist[i] = 0;
    __syncthreads();
    if (tid == 0) {
        for (int i = 0; i < N_; ++i) {
            const int l = sli[i], r = sri[i];
            const int a = (l < 0) ? 0 : (int)slv[l];
            const int c = (r < 0) ? 0 : (int)slv[r];
            const int lv = 1 + (a > c ? a : c);
            slv[i] = (unsigned short)lv;
            shist[lv]++;
        }
    }
    __syncthreads();
    for (int i = tid; i < N_; i += 128) g_lvl[b * N_ + i] = slv[i];
    for (int l = tid; l < MAXL; l += 128) g_cntb[l * B_ + b] = shist[l];
}

extern "C" __global__ void __launch_bounds__(256)
k_prefix()
{
    __shared__ int tot[MAXL];
    __shared__ int offs[MAXL + 1];
    const int tid = threadIdx.x;
    for (int l = tid; l < MAXL; l += 256) {
        int run = 0; const int base = l * B_;
        #pragma unroll 4
        for (int b = 0; b < B_; ++b) { const int c = g_cntb[base + b]; g_base[base + b] = run; run += c; }
        tot[l] = run;
    }
    __syncthreads();
    if (tid == 0) {
        int run = 0, mx = 1;
        for (int l = 0; l < MAXL; ++l) { offs[l] = run; run += tot[l]; if (tot[l] > 0) mx = l; }
        offs[MAXL] = run;
        g_nlv = mx;
    }
    __syncthreads();
    for (int idx = tid; idx < MAXL * B_; idx += 256) g_base[idx] += offs[idx >> 8];
    for (int l = tid; l <= MAXL; l += 256) g_off[l] = offs[l];
}

// counting-sort scatter + Wh transpose/pack (merged)
extern "C" __global__ void __launch_bounds__(128)
k_scatter(const float* __restrict__ W_ih)
{
    __shared__ unsigned short slv[N_];
    __shared__ int cur[MAXL];
    __shared__ int pos[N_];
    const int b = blockIdx.x, tid = threadIdx.x;
    for (int i = tid; i < N_; i += 128) slv[i] = g_lvl[b * N_ + i];
    for (int l = tid; l < MAXL; l += 128) cur[l] = g_base[l * B_ + b];
    __syncthreads();
    if (tid == 0)
        for (int i = 0; i < N_; ++i) { const int l = slv[i]; pos[i] = cur[l]++; }
    __syncthreads();
    for (int i = tid; i < N_; i += 128) g_nodes[pos[i]] = (b << 9) | i;

    // ---- Wh transpose + fp16 pack, fragment layout for mma.B ----
    // u32 index = ((n_tile*16 + kpair)*32 + lane)*4 + ko*2 + word
    for (int t = tid; t < 2 * HID_; t += 128) {
        const int n = 2 * b + (t >> 9);          // 2 n-rows per block
        const int k = t & (HID_ - 1);
        const float w = W_ih[(size_t)(IN_ + k) * HID_ + n];
        const __half h = __float2half_rn(w);
        const int n_tile = n >> 3, kpair = k >> 5, ko = (k >> 4) & 1;
        const int lane = ((n & 7) << 2) | ((k >> 1) & 3);
        const int word = (k >> 3) & 1, elem = k & 1;
        const size_t u32i = ((size_t)(n_tile * 16 + kpair) * 32 + lane) * 4 + ko * 2 + word;
        g_Wb[u32i * 2 + elem] = h;
    }
}

// ============================================================================
// Grid-wide software barrier
// ============================================================================
__device__ __forceinline__ void grid_barrier(unsigned tgt, unsigned nct)
{
    __syncthreads();
    if (threadIdx.x == 0) {
        __threadfence();
        const unsigned a = atomicAdd(&g_barcnt, 1u);
        if (a == nct - 1u) {
            g_barcnt = 0u;
            __threadfence();
            atomicExch(&g_epoch, tgt);
        } else {
            unsigned e;
            do {
                asm volatile("ld.acquire.gpu.u32 %0, [%1];"
                             : "=r"(e) : "l"((unsigned*)&g_epoch) : "memory");
                if (e >= tgt) break;
                __nanosleep(64u);
            } while (true);
        }
    }
    __syncthreads();
}

// ============================================================================
// Main persistent kernel: level-parallel single-pass fp16 HMMA GEMM + tanh.
// Item: 64 nodes x 128 cols. Warp tile: 32 rows x 32 cols (2x4 warp grid).
// A = fp16(h_l + h_r), double-buffered SMEM, K chunks of 128.
// W = fp16 (single pass). Error sources: A and W fp16 rounding (~2^-12 each),
// strongly damped by the tanh recurrence (measured ~50x in R12).
// ============================================================================
extern "C" __global__ void __launch_bounds__(THR_MAIN, 2)
rnn_main(const int* __restrict__ L, const int* __restrict__ R,
         const int* __restrict__ V, const float* __restrict__ W_ih,
         const float* __restrict__ b_ih)
{
    extern __shared__ char sm[];
    const uint32_t smem_base = smem_u32(sm);
    float* bih = (float*)(sm + SM_BIH);
    int*   il  = (int*)(sm + SM_META);
    int*   ir  = il + MT;
    int*   iv  = ir + MT;
    int*   io  = iv + MT;

    const int tid  = threadIdx.x;
    const int wid  = tid >> 5, lane = tid & 31;

    for (int i = tid; i < HID_; i += THR_MAIN) bih[i] = b_ih[i];

    // warp tiling: 2 row groups x 4 col groups (32 cols each)
    const int wm  = (wid & 1) * 32;          // warp row base
    const int wgn = wid >> 1;                // col group (0..3)
    const uint32_t a_lane = (uint32_t)((lane & 15) * A_STRIDE + (lane >> 4) * 16);
    const uint32_t aoffm0 = (uint32_t)(wm * A_STRIDE);
    const uint32_t aoffm1 = (uint32_t)((wm + 16) * A_STRIDE);

    const int nlv = g_nlv;
    const unsigned nct = gridDim.x;

    // gather mapping: row = tid>>2, k-quarter = tid&3 (32 floats)
    const int grow = tid >> 2, gks = tid & 3;

    #define GATHER(c, bf)                                                        \
    {                                                                            \
        const float4* pl = (const float4*)(g_H + (size_t)il[grow] * HID_)        \
                           + ((c) * 32 + gks * 8);                               \
        const float4* pr = (const float4*)(g_H + (size_t)ir[grow] * HID_)        \
                           + ((c) * 32 + gks * 8);                               \
        char* dh = sm + SM_A + (bf) * A_BUFSZ + grow * A_STRIDE + gks * 64;      \
        _Pragma("unroll")                                                        \
        for (int j = 0; j < 2; ++j) {                                            \
            float4 la[4], ra[4];                                                 \
            _Pragma("unroll")                                                    \
            for (int q = 0; q < 4; ++q) {                                        \
                la[q] = __ldcg(pl + j * 4 + q);                                  \
                ra[q] = __ldcg(pr + j * 4 + q);                                  \
            }                                                                    \
            uint32_t hw[8];                                                      \
            _Pragma("unroll")                                                    \
            for (int q = 0; q < 4; ++q) {                                        \
                const __half2 h01 = __floats2half2_rn(la[q].x + ra[q].x,         \
                                                      la[q].y + ra[q].y);        \
                const __half2 h23 = __floats2half2_rn(la[q].z + ra[q].z,         \
                                                      la[q].w + ra[q].w);        \
                hw[q * 2 + 0] = *(const uint32_t*)&h01;                          \
                hw[q * 2 + 1] = *(const uint32_t*)&h23;                          \
            }                                                                    \
            ((uint4*)dh)[j * 2 + 0] = make_uint4(hw[0], hw[1], hw[2], hw[3]);    \
            ((uint4*)dh)[j * 2 + 1] = make_uint4(hw[4], hw[5], hw[6], hw[7]);    \
        }                                                                        \
    }

    for (int lvl = 1; lvl <= nlv; ++lvl) {
        const int s = g_off[lvl], e = g_off[lvl + 1];
        const int items = ((e - s + MT - 1) >> 6) * 4;
        for (int w = blockIdx.x; w < items; w += (int)nct) {
            const int rt = w >> 2, hp = w & 3;            // row tile / col quarter
            const int t0 = s + rt * MT;
            const int ntb = hp * 16 + wgn * 4;            // global n-tile base

            // ---- node metadata ----
            if (tid < MT) {
                const int gi = t0 + tid;
                if (gi < e) {
                    const int nd = g_nodes[gi];
                    const int b = nd >> 9, i = nd & (N_ - 1);
                    int l = L[b * N_ + i]; if (l < 0) l = N_;
                    int r = R[b * N_ + i]; if (r < 0) r = N_;
                    il[tid] = b * (N_ + 1) + l;
                    ir[tid] = b * (N_ + 1) + r;
                    iv[tid] = V[b * N_ + i];
                    io[tid] = b * (N_ + 1) + i;
                } else {
                    il[tid] = N_;     // zero sentinel row (b=0)
                    ir[tid] = N_;
                    iv[tid] = -1;
                }
            }
            __syncthreads();

            float acc[2][4][4];
            #pragma unroll
            for (int mt = 0; mt < 2; ++mt)
                #pragma unroll
                for (int nt = 0; nt < 4; ++nt)
                    #pragma unroll
                    for (int q = 0; q < 4; ++q) acc[mt][nt][q] = 0.0f;

            GATHER(0, 0)
            __syncthreads();

            #pragma unroll
            for (int c = 0; c < 4; ++c) {
                if (c < 3) GATHER(c + 1, (c + 1) & 1)

                const uint32_t abA = smem_base + SM_A + (uint32_t)((c & 1) * A_BUFSZ) + a_lane;

                #pragma unroll
                for (int kp = 0; kp < 4; ++kp) {
                    const int gkp = c * 4 + kp;
                    // A fragments for both k16 halves
                    uint32_t ah[2][2][4];                // [ks2][mtile][4]
                    #pragma unroll
                    for (int ks2 = 0; ks2 < 2; ++ks2) {
                        const uint32_t koff = (uint32_t)((kp * 2 + ks2) * 32);
                        ldsm4(ah[ks2][0], abA + aoffm0 + koff);
                        ldsm4(ah[ks2][1], abA + aoffm1 + koff);
                    }
                    // single pass: A x W
                    uint4 bfr[4];
                    {
                        const uint4* bph = (const uint4*)g_Wb
                            + ((size_t)ntb * 16 + gkp) * 32 + lane;
                        #pragma unroll
                        for (int nt = 0; nt < 4; ++nt)
                            bfr[nt] = __ldg(bph + (size_t)nt * 512);
                    }
                    #pragma unroll
                    for (int ks2 = 0; ks2 < 2; ++ks2)
                        #pragma unroll
                        for (int nt = 0; nt < 4; ++nt) {
                            const uint32_t b0 = ks2 ? bfr[nt].z : bfr[nt].x;
                            const uint32_t b1 = ks2 ? bfr[nt].w : bfr[nt].y;
                            mma16816(acc[0][nt], ah[ks2][0], b0, b1);
                            mma16816(acc[1][nt], ah[ks2][1], b0, b1);
                        }
                }
                __syncthreads();
            }

            // ---- epilogue: + Wx[value] + b_ih, fast tanh, store h ----
            #pragma unroll
            for (int mt = 0; mt < 2; ++mt) {
                const int r1 = wm + mt * 16 + (lane >> 2);
                const int r2 = r1 + 8;
                const int v1 = iv[r1], v2 = iv[r2];
                const int o1 = io[r1], o2 = io[r2];
                #pragma unroll
                for (int nt = 0; nt < 4; ++nt) {
                    const int gcol = hp * NQ + wgn * 32 + nt * 8 + (lane & 3) * 2;
                    const float2 bv = *(const float2*)(bih + gcol);
                    if (v1 >= 0) {
                        const float2 wx = __ldg((const float2*)(W_ih + (size_t)v1 * HID_ + gcol));
                        float2 o;
                        o.x = ftanh(acc[mt][nt][0] + wx.x + bv.x);
                        o.y = ftanh(acc[mt][nt][1] + wx.y + bv.y);
                        *(float2*)(g_H + (size_t)o1 * HID_ + gcol) = o;
                    }
                    if (v2 >= 0) {
                        const float2 wx = __ldg((const float2*)(W_ih + (size_t)v2 * HID_ + gcol));
                        float2 o;
                        o.x = ftanh(acc[mt][nt][2] + wx.x + bv.x);
                        o.y = ftanh(acc[mt][nt][3] + wx.y + bv.y);
                        *(float2*)(g_H + (size_t)o2 * HID_ + gcol) = o;
                    }
                }
            }
            __syncthreads();   // meta/A reuse protection for next item
        }
        grid_barrier((unsigned)lvl, nct);
    }
    #undef GATHER
}

// ============================================================================
// Barrier state reset (graph-replay determinism)
// ============================================================================
extern "C" __global__ void k_reset()
{
    if (threadIdx.x == 0) { g_epoch = 0u; g_barcnt = 0u; }
}

// ============================================================================
// Output kernel: logits = h_root @ W_o + b_o, then log_softmax
// ============================================================================
extern "C" __global__ void __launch_bounds__(64)
rnn_out(const float* __restrict__ W_o,
        const float* __restrict__ b_o,
        float* __restrict__ out)
{
    __shared__ float hs[HID_];
    __shared__ float lg[OUT_];
    __shared__ float lse;
    const int b   = blockIdx.x;
    const int tid = threadIdx.x;

    const float* hrow = g_H + ((size_t)b * (N_ + 1) + (N_ - 1)) * HID_;
    #pragma unroll
    for (int j = 0; j < 2; ++j) {
        const float4 v = *(const float4*)(hrow + tid * 8 + j * 4);
        *(float4*)(hs + tid * 8 + j * 4) = v;
    }
    __syncthreads();

    if (tid < OUT_) {
        float acc = b_o[tid];
        #pragma unroll 8
        for (int k = 0; k < HID_; ++k)
            acc = fmaf(hs[k], __ldg(W_o + (size_t)k * OUT_ + tid), acc);
        lg[tid] = acc;
    }
    __syncthreads();

    if (tid == 0) {
        float m = -1e30f;
        for (int j = 0; j < OUT_; ++j) m = fmaxf(m, lg[j]);
        float ssum = 0.f;
        for (int j = 0; j < OUT_; ++j) ssum += expf(lg[j] - m);
        lse = m + logf(ssum);
    }
    __syncthreads();

    if (tid < OUT_) out[(size_t)b * OUT_ + tid] = lg[tid] - lse;
}

// ============================================================================
// Launcher: 6 graph nodes, capturable, allocation-free.
// ============================================================================
extern "C" void kernel_launch(void* const* d_in, const int* in_sizes, int n_in,
                              void* d_out, int out_size)
{
    (void)in_sizes; (void)n_in; (void)out_size;
    const int*   left  = (const int*)d_in[0];
    const int*   right = (const int*)d_in[1];
    const int*   vals  = (const int*)d_in[2];
    const float* W_ih  = (const float*)d_in[3];
    const float* b_ih  = (const float*)d_in[4];
    const float* W_o   = (const float*)d_in[5];
    const float* b_o   = (const float*)d_in[6];
    float*       out   = (float*)d_out;

    cudaFuncSetAttribute(rnn_main,
                         cudaFuncAttributeMaxDynamicSharedMemorySize, SMEM_MAIN);

    k_levels<<<B_, 128>>>(left, right);
    k_prefix<<<1, 256>>>();
    k_scatter<<<B_, 128>>>(W_ih);
    rnn_main<<<GRID_MAIN, THR_MAIN, SMEM_MAIN>>>(left, right, vals, W_ih, b_ih);
    k_reset<<<1, 1>>>();
    rnn_out<<<B_, 64>>>(W_o, b_o, out);
}

// round 15
// speedup vs baseline: 12.8808x; 1.4451x over previous
#include <cuda_runtime.h>
#include <cuda_fp16.h>
#include <math.h>
#include <stdint.h>

// Problem constants
#define B_    256
#define N_    512
#define HID_  512
#define IN_   57
#define OUT_  57

#define MAXL      513
#define GRID_MAIN 296            // 2 CTAs/SM x 148 SMs, co-resident
#define THR_MAIN  256
#define MT        64             // nodes (rows) per item
#define NQ        128            // cols per item (quarter of N)

// ---------------- device globals ----------------
__device__ __half         g_H[(size_t)B_ * (N_ + 1) * HID_];   // fp16 h; row N_ (b=0) = zero sentinel
__device__ __half         g_Wb[HID_ * HID_];      // fragment-packed Wh^T (fp16)
__device__ unsigned short g_lvl[B_ * N_];
__device__ int            g_cntb[MAXL * B_];
__device__ int            g_base[MAXL * B_];
__device__ int            g_off[MAXL + 1];
__device__ int            g_nodes[B_ * N_];
__device__ int            g_nlv;
__device__ unsigned       g_barcnt;
__device__ unsigned       g_epoch;

// ---------------- SMEM layout ----------------
// A plane (fp16): [2 buf][64 rows][136 fp16] row stride 272 B
#define A_STRIDE 272
#define A_BUFSZ  (MT * A_STRIDE)         // 17408
#define SM_A     0                       // 2 * 17408 = 34816
#define SM_BIH   34816                   // 512 f32 = 2048
#define SM_META  36864                   // il/ir/iv/io [64] each = 1024
#define SMEM_MAIN 37888                  // x2 CTAs = 75776 B/SM

// ---------------- PTX helpers (baseline ISA only) ----------------
__device__ __forceinline__ void mma16816(float* d, const uint32_t* a,
                                         uint32_t b0, uint32_t b1) {
    asm volatile(
        "mma.sync.aligned.m16n8k16.row.col.f32.f16.f16.f32 "
        "{%0,%1,%2,%3}, {%4,%5,%6,%7}, {%8,%9}, {%0,%1,%2,%3};\n"
        : "+f"(d[0]), "+f"(d[1]), "+f"(d[2]), "+f"(d[3])
        : "r"(a[0]), "r"(a[1]), "r"(a[2]), "r"(a[3]), "r"(b0), "r"(b1));
}
__device__ __forceinline__ void ldsm4(uint32_t* r, uint32_t a) {
    asm volatile("ldmatrix.sync.aligned.m8n8.x4.shared.b16 {%0,%1,%2,%3}, [%4];\n"
        : "=r"(r[0]), "=r"(r[1]), "=r"(r[2]), "=r"(r[3]) : "r"(a));
}
__device__ __forceinline__ uint32_t smem_u32(const void* p) {
    return (uint32_t)__cvta_generic_to_shared(p);
}

// FFMA-only tanh: tanh(x) = 1 - 2/(e^{2x}+1); exp2 via round-trick + deg-7
// Taylor; reciprocal via bit-trick seed + 3 Newton. No MUFU, no CVT.
__device__ __forceinline__ float ftanh(float x) {
    float t = fminf(fmaxf(x, -15.0f), 15.0f);
    float z = t * 2.8853900817779268f;           // 2*log2(e)*x
    float zk = z + 12582912.0f;                   // round-to-nearest-even
    float k  = zk - 12582912.0f;
    float f  = z - k;                             // f in [-0.5, 0.5]
    float p = 1.5252733814e-5f;
    p = fmaf(p, f, 1.5403530394e-4f);
    p = fmaf(p, f, 1.3333558146e-3f);
    p = fmaf(p, f, 9.6181291076e-3f);
    p = fmaf(p, f, 5.5504108664e-2f);
    p = fmaf(p, f, 2.4022650696e-1f);
    p = fmaf(p, f, 6.9314718056e-1f);
    p = fmaf(p, f, 1.0f);
    const int ib = __float_as_int(zk);
    const float sc = __int_as_float((ib + (127 - 0x4B400000)) << 23);   // 2^k
    const float E = p * sc;                       // e^{2x}
    const float d = E + 1.0f;
    float r = __int_as_float(0x7EF311C3 - __float_as_int(d));
    r = r * fmaf(-d, r, 2.0f);
    r = r * fmaf(-d, r, 2.0f);
    r = r * fmaf(-d, r, 2.0f);
    return fmaf(-2.0f, r, 1.0f);
}

// ============================================================================
// Prep kernels
// ============================================================================
extern "C" __global__ void __launch_bounds__(128)
k_levels(const int* __restrict__ L, const int* __restrict__ R)
{
    __shared__ int sli[N_], sri[N_], shist[MAXL];
    __shared__ unsigned short slv[N_];
    const int b = blockIdx.x, tid = threadIdx.x;
    for (int i = tid; i < N_; i += 128) { sli[i] = L[b * N_ + i]; sri[i] = R[b * N_ + i]; }
    for (int i = tid; i < MAXL; i += 128) shist[i] = 0;
    __syncthreads();
    if (tid == 0) {
        for (int i = 0; i < N_; ++i) {
            const int l = sli[i], r = sri[i];
            const int a = (l < 0) ? 0 : (int)slv[l];
            const int c = (r < 0) ? 0 : (int)slv[r];
            const int lv = 1 + (a > c ? a : c);
            slv[i] = (unsigned short)lv;
            shist[lv]++;
        }
    }
    __syncthreads();
    for (int i = tid; i < N_; i += 128) g_lvl[b * N_ + i] = slv[i];
    for (int l = tid; l < MAXL; l += 128) g_cntb[l * B_ + b] = shist[l];
}

extern "C" __global__ void __launch_bounds__(256)
k_prefix()
{
    __shared__ int tot[MAXL];
    __shared__ int offs[MAXL + 1];
    const int tid = threadIdx.x;
    for (int l = tid; l < MAXL; l += 256) {
        int run = 0; const int base = l * B_;
        #pragma unroll 4
        for (int b = 0; b < B_; ++b) { const int c = g_cntb[base + b]; g_base[base + b] = run; run += c; }
        tot[l] = run;
    }
    __syncthreads();
    if (tid == 0) {
        int run = 0, mx = 1;
        for (int l = 0; l < MAXL; ++l) { offs[l] = run; run += tot[l]; if (tot[l] > 0) mx = l; }
        offs[MAXL] = run;
        g_nlv = mx;
    }
    __syncthreads();
    for (int idx = tid; idx < MAXL * B_; idx += 256) g_base[idx] += offs[idx >> 8];
    for (int l = tid; l <= MAXL; l += 256) g_off[l] = offs[l];
}

// counting-sort scatter + Wh transpose/pack (merged)
extern "C" __global__ void __launch_bounds__(128)
k_scatter(const float* __restrict__ W_ih)
{
    __shared__ unsigned short slv[N_];
    __shared__ int cur[MAXL];
    __shared__ int pos[N_];
    const int b = blockIdx.x, tid = threadIdx.x;
    for (int i = tid; i < N_; i += 128) slv[i] = g_lvl[b * N_ + i];
    for (int l = tid; l < MAXL; l += 128) cur[l] = g_base[l * B_ + b];
    __syncthreads();
    if (tid == 0)
        for (int i = 0; i < N_; ++i) { const int l = slv[i]; pos[i] = cur[l]++; }
    __syncthreads();
    for (int i = tid; i < N_; i += 128) g_nodes[pos[i]] = (b << 9) | i;

    // ---- Wh transpose + fp16 pack, fragment layout for mma.B ----
    // u32 index = ((n_tile*16 + kpair)*32 + lane)*4 + ko*2 + word
    for (int t = tid; t < 2 * HID_; t += 128) {
        const int n = 2 * b + (t >> 9);          // 2 n-rows per block
        const int k = t & (HID_ - 1);
        const float w = W_ih[(size_t)(IN_ + k) * HID_ + n];
        const __half h = __float2half_rn(w);
        const int n_tile = n >> 3, kpair = k >> 5, ko = (k >> 4) & 1;
        const int lane = ((n & 7) << 2) | ((k >> 1) & 3);
        const int word = (k >> 3) & 1, elem = k & 1;
        const size_t u32i = ((size_t)(n_tile * 16 + kpair) * 32 + lane) * 4 + ko * 2 + word;
        g_Wb[u32i * 2 + elem] = h;
    }
}

// ============================================================================
// Grid-wide software barrier (pure acquire-spin; CTAs co-resident)
// ============================================================================
__device__ __forceinline__ void grid_barrier(unsigned tgt, unsigned nct)
{
    __syncthreads();
    if (threadIdx.x == 0) {
        __threadfence();
        const unsigned a = atomicAdd(&g_barcnt, 1u);
        if (a == nct - 1u) {
            g_barcnt = 0u;
            __threadfence();
            atomicExch(&g_epoch, tgt);
        } else {
            unsigned e;
            do {
                asm volatile("ld.acquire.gpu.u32 %0, [%1];"
                             : "=r"(e) : "l"((unsigned*)&g_epoch) : "memory");
            } while (e < tgt);
        }
    }
    __syncthreads();
}

// ============================================================================
// Main persistent kernel: level-parallel single-pass fp16 HMMA GEMM + tanh.
// Item: 64 nodes x 128 cols. Warp tile: 32 rows x 32 cols (2x4 warp grid).
// g_H is fp16: gather = uint4 loads + __hadd2 (no cvt), half the bytes.
// A = h_l + h_r (fp16 add), double-buffered SMEM, K chunks of 128.
// W = fp16 single pass.
// ============================================================================
extern "C" __global__ void __launch_bounds__(THR_MAIN, 2)
rnn_main(const int* __restrict__ L, const int* __restrict__ R,
         const int* __restrict__ V, const float* __restrict__ W_ih,
         const float* __restrict__ b_ih)
{
    extern __shared__ char sm[];
    const uint32_t smem_base = smem_u32(sm);
    float* bih = (float*)(sm + SM_BIH);
    int*   il  = (int*)(sm + SM_META);
    int*   ir  = il + MT;
    int*   iv  = ir + MT;
    int*   io  = iv + MT;

    const int tid  = threadIdx.x;
    const int wid  = tid >> 5, lane = tid & 31;

    for (int i = tid; i < HID_; i += THR_MAIN) bih[i] = b_ih[i];

    // warp tiling: 2 row groups x 4 col groups (32 cols each)
    const int wm  = (wid & 1) * 32;          // warp row base
    const int wgn = wid >> 1;                // col group (0..3)
    const uint32_t a_lane = (uint32_t)((lane & 15) * A_STRIDE + (lane >> 4) * 16);
    const uint32_t aoffm0 = (uint32_t)(wm * A_STRIDE);
    const uint32_t aoffm1 = (uint32_t)((wm + 16) * A_STRIDE);

    const int nlv = g_nlv;
    const unsigned nct = gridDim.x;

    // gather mapping: row = tid>>2, k-quarter = tid&3 (32 halves = 4 uint4)
    const int grow = tid >> 2, gks = tid & 3;

    #define GATHER(c, bf)                                                        \
    {                                                                            \
        const uint4* pl = (const uint4*)(g_H + (size_t)il[grow] * HID_)          \
                          + ((c) * 16 + gks * 4);                                \
        const uint4* pr = (const uint4*)(g_H + (size_t)ir[grow] * HID_)          \
                          + ((c) * 16 + gks * 4);                                \
        uint4 la[4], ra[4];                                                      \
        _Pragma("unroll")                                                        \
        for (int q = 0; q < 4; ++q) { la[q] = __ldcg(pl + q); ra[q] = __ldcg(pr + q); } \
        char* dh = sm + SM_A + (bf) * A_BUFSZ + grow * A_STRIDE + gks * 64;      \
        _Pragma("unroll")                                                        \
        for (int q = 0; q < 4; ++q) {                                            \
            const __half2* a2 = (const __half2*)&la[q];                          \
            const __half2* b2 = (const __half2*)&ra[q];                          \
            __half2 s0 = __hadd2(a2[0], b2[0]);                                  \
            __half2 s1 = __hadd2(a2[1], b2[1]);                                  \
            __half2 s2 = __hadd2(a2[2], b2[2]);                                  \
            __half2 s3 = __hadd2(a2[3], b2[3]);                                  \
            ((uint4*)dh)[q] = make_uint4(*(uint32_t*)&s0, *(uint32_t*)&s1,       \
                                         *(uint32_t*)&s2, *(uint32_t*)&s3);      \
        }                                                                        \
    }

    for (int lvl = 1; lvl <= nlv; ++lvl) {
        const int s = g_off[lvl], e = g_off[lvl + 1];
        const int items = ((e - s + MT - 1) >> 6) * 4;
        for (int w = blockIdx.x; w < items; w += (int)nct) {
            const int rt = w >> 2, hp = w & 3;            // row tile / col quarter
            const int t0 = s + rt * MT;
            const int ntb = hp * 16 + wgn * 4;            // global n-tile base

            // ---- node metadata ----
            if (tid < MT) {
                const int gi = t0 + tid;
                if (gi < e) {
                    const int nd = g_nodes[gi];
                    const int b = nd >> 9, i = nd & (N_ - 1);
                    int l = L[b * N_ + i]; if (l < 0) l = N_;
                    int r = R[b * N_ + i]; if (r < 0) r = N_;
                    il[tid] = b * (N_ + 1) + l;
                    ir[tid] = b * (N_ + 1) + r;
                    iv[tid] = V[b * N_ + i];
                    io[tid] = b * (N_ + 1) + i;
                } else {
                    il[tid] = N_;     // zero sentinel row (b=0)
                    ir[tid] = N_;
                    iv[tid] = -1;
                }
            }
            __syncthreads();

            float acc[2][4][4];
            #pragma unroll
            for (int mt = 0; mt < 2; ++mt)
                #pragma unroll
                for (int nt = 0; nt < 4; ++nt)
                    #pragma unroll
                    for (int q = 0; q < 4; ++q) acc[mt][nt][q] = 0.0f;

            GATHER(0, 0)
            __syncthreads();

            #pragma unroll
            for (int c = 0; c < 4; ++c) {
                if (c < 3) GATHER(c + 1, (c + 1) & 1)

                const uint32_t abA = smem_base + SM_A + (uint32_t)((c & 1) * A_BUFSZ) + a_lane;

                #pragma unroll
                for (int kp = 0; kp < 4; ++kp) {
                    const int gkp = c * 4 + kp;
                    // A fragments for both k16 halves
                    uint32_t ah[2][2][4];                // [ks2][mtile][4]
                    #pragma unroll
                    for (int ks2 = 0; ks2 < 2; ++ks2) {
                        const uint32_t koff = (uint32_t)((kp * 2 + ks2) * 32);
                        ldsm4(ah[ks2][0], abA + aoffm0 + koff);
                        ldsm4(ah[ks2][1], abA + aoffm1 + koff);
                    }
                    // single pass: A x W
                    uint4 bfr[4];
                    {
                        const uint4* bph = (const uint4*)g_Wb
                            + ((size_t)ntb * 16 + gkp) * 32 + lane;
                        #pragma unroll
                        for (int nt = 0; nt < 4; ++nt)
                            bfr[nt] = __ldg(bph + (size_t)nt * 512);
                    }
                    #pragma unroll
                    for (int ks2 = 0; ks2 < 2; ++ks2)
                        #pragma unroll
                        for (int nt = 0; nt < 4; ++nt) {
                            const uint32_t b0 = ks2 ? bfr[nt].z : bfr[nt].x;
                            const uint32_t b1 = ks2 ? bfr[nt].w : bfr[nt].y;
                            mma16816(acc[0][nt], ah[ks2][0], b0, b1);
                            mma16816(acc[1][nt], ah[ks2][1], b0, b1);
                        }
                }
                __syncthreads();
            }

            // ---- epilogue: + Wx[value] + b_ih, fast tanh, store h (fp16) ----
            #pragma unroll
            for (int mt = 0; mt < 2; ++mt) {
                const int r1 = wm + mt * 16 + (lane >> 2);
                const int r2 = r1 + 8;
                const int v1 = iv[r1], v2 = iv[r2];
                const int o1 = io[r1], o2 = io[r2];
                #pragma unroll
                for (int nt = 0; nt < 4; ++nt) {
                    const int gcol = hp * NQ + wgn * 32 + nt * 8 + (lane & 3) * 2;
                    const float2 bv = *(const float2*)(bih + gcol);
                    if (v1 >= 0) {
                        const float2 wx = __ldg((const float2*)(W_ih + (size_t)v1 * HID_ + gcol));
                        const __half2 o2h = __floats2half2_rn(
                            ftanh(acc[mt][nt][0] + wx.x + bv.x),
                            ftanh(acc[mt][nt][1] + wx.y + bv.y));
                        *(__half2*)(g_H + (size_t)o1 * HID_ + gcol) = o2h;
                    }
                    if (v2 >= 0) {
                        const float2 wx = __ldg((const float2*)(W_ih + (size_t)v2 * HID_ + gcol));
                        const __half2 o2h = __floats2half2_rn(
                            ftanh(acc[mt][nt][2] + wx.x + bv.x),
                            ftanh(acc[mt][nt][3] + wx.y + bv.y));
                        *(__half2*)(g_H + (size_t)o2 * HID_ + gcol) = o2h;
                    }
                }
            }
            __syncthreads();   // meta/A reuse protection for next item
        }
        grid_barrier((unsigned)lvl, nct);
    }
    #undef GATHER
}

// ============================================================================
// Barrier state reset (graph-replay determinism)
// ============================================================================
extern "C" __global__ void k_reset()
{
    if (threadIdx.x == 0) { g_epoch = 0u; g_barcnt = 0u; }
}

// ============================================================================
// Output kernel: logits = h_root @ W_o + b_o, then log_softmax
// ============================================================================
extern "C" __global__ void __launch_bounds__(64)
rnn_out(const float* __restrict__ W_o,
        const float* __restrict__ b_o,
        float* __restrict__ out)
{
    __shared__ float hs[HID_];
    __shared__ float lg[OUT_];
    __shared__ float lse;
    const int b   = blockIdx.x;
    const int tid = threadIdx.x;

    const __half* hrow = g_H + ((size_t)b * (N_ + 1) + (N_ - 1)) * HID_;
    {
        const uint4 v = *(const uint4*)(hrow + tid * 8);
        const __half2* h2 = (const __half2*)&v;
        #pragma unroll
        for (int j = 0; j < 4; ++j) {
            const float2 f = __half22float2(h2[j]);
            hs[tid * 8 + j * 2 + 0] = f.x;
            hs[tid * 8 + j * 2 + 1] = f.y;
        }
    }
    __syncthreads();

    if (tid < OUT_) {
        float acc = b_o[tid];
        #pragma unroll 8
        for (int k = 0; k < HID_; ++k)
            acc = fmaf(hs[k], __ldg(W_o + (size_t)k * OUT_ + tid), acc);
        lg[tid] = acc;
    }
    __syncthreads();

    if (tid == 0) {
        float m = -1e30f;
        for (int j = 0; j < OUT_; ++j) m = fmaxf(m, lg[j]);
        float ssum = 0.f;
        for (int j = 0; j < OUT_; ++j) ssum += expf(lg[j] - m);
        lse = m + logf(ssum);
    }
    __syncthreads();

    if (tid < OUT_) out[(size_t)b * OUT_ + tid] = lg[tid] - lse;
}

// ============================================================================
// Launcher: 6 graph nodes, capturable, allocation-free.
// ============================================================================
extern "C" void kernel_launch(void* const* d_in, const int* in_sizes, int n_in,
                              void* d_out, int out_size)
{
    (void)in_sizes; (void)n_in; (void)out_size;
    const int*   left  = (const int*)d_in[0];
    const int*   right = (const int*)d_in[1];
    const int*   vals  = (const int*)d_in[2];
    const float* W_ih  = (const float*)d_in[3];
    const float* b_ih  = (const float*)d_in[4];
    const float* W_o   = (const float*)d_in[5];
    const float* b_o   = (const float*)d_in[6];
    float*       out   = (float*)d_out;

    cudaFuncSetAttribute(rnn_main,
                         cudaFuncAttributeMaxDynamicSharedMemorySize, SMEM_MAIN);

    k_levels<<<B_, 128>>>(left, right);
    k_prefix<<<1, 256>>>();
    k_scatter<<<B_, 128>>>(W_ih);
    rnn_main<<<GRID_MAIN, THR_MAIN, SMEM_MAIN>>>(left, right, vals, W_ih, b_ih);
    k_reset<<<1, 1>>>();
    rnn_out<<<B_, 64>>>(W_o, b_o, out);
}